// round 5
// baseline (speedup 1.0000x reference)
#include <cuda_runtime.h>
#include <math.h>

#define B_  4
#define H_  16
#define NT  512
#define NL  512
#define E_  64
#define P_  1024
#define BH  (B_*H_)
#define PRIOR 8.0f

typedef unsigned long long u64;

// packed f32x2 helpers (Blackwell: fma.rn.f32x2 = 2 fp32 FMA lanes per issue)
__device__ __forceinline__ u64 pk2(float v) {
    u64 r; asm("mov.b64 %0, {%1, %1};" : "=l"(r) : "f"(v)); return r;
}
__device__ __forceinline__ void fma2(u64 &d, u64 a, u64 b) {
    asm("fma.rn.f32x2 %0, %1, %2, %0;" : "+l"(d) : "l"(a), "l"(b));
}
__device__ __forceinline__ float2 up2(u64 v) {
    float2 r; asm("mov.b64 {%0, %1}, %2;" : "=f"(r.x), "=f"(r.y) : "l"(v)); return r;
}

// ---------------- scratch ----------------
__device__ float g_r [B_*NL*P_];   // mu / bv
__device__ float g_c1[B_*NL*P_];   // var / bv
__device__ float g_c2[B_*NL*P_];   // 8*mu / bv
__device__ float g_add[BH*NL];     // per-(bh,n) additive logit (-inf if masked)
__device__ float g_D [BH*NL*E_];   // c2 @ w_v^T + b_v^T   [bh][n][e]
__device__ float g_G [BH*NT*P_];   // (attn @ c1) * U      [bh][m][p]

// ---------------- K0: per-(b,n) precompute + reductions ----------------
__global__ __launch_bounds__(256) void k_prep(
    const float* __restrict__ mu, const float* __restrict__ logvar,
    const float* __restrict__ pi, const unsigned char* __restrict__ mask)
{
    int n = blockIdx.x, b = blockIdx.y;
    int base = (b*NL + n)*P_;
    int t = threadIdx.x;
    float s2 = 0.f, s3 = 0.f;
#pragma unroll
    for (int i = 0; i < 4; i++) {
        int p = t + i*256;
        float m  = mu[base+p];
        float v  = expf(logvar[base+p]);
        float bv = v + PRIOR;
        float inv = 1.0f / bv;
        g_r [base+p] = m * inv;
        g_c1[base+p] = v * inv;
        g_c2[base+p] = PRIOR * m * inv;
        s2 += m * m * inv;
        s3 += logf(bv);
    }
    __shared__ float red2[8], red3[8];
#pragma unroll
    for (int o = 16; o > 0; o >>= 1) {
        s2 += __shfl_down_sync(0xffffffffu, s2, o);
        s3 += __shfl_down_sync(0xffffffffu, s3, o);
    }
    if ((t & 31) == 0) { red2[t>>5] = s2; red3[t>>5] = s3; }
    __syncthreads();
    __shared__ float sbase;
    if (t == 0) {
        float a2 = 0.f, a3 = 0.f;
        for (int i = 0; i < 8; i++) { a2 += red2[i]; a3 += red3[i]; }
        float piv = pi[b*NL + n];
        float pc  = fmaxf(piv, 1.17549435e-38f);
        sbase = logf(pc) - 0.5f*a2 - 0.5f*a3;
    }
    __syncthreads();
    if (t < H_) {
        float piv = pi[b*NL + n];
        bool msk = (mask[(b*H_ + t)*NL + n] != 0) || (piv <= 0.f);
        g_add[(b*H_ + t)*NL + n] = msk ? -INFINITY : sbase;
    }
}

// ---------------- K_D: D[bh][n][e] = c2[b] @ w_v[h]^T + b_v[h]^T ----------------
__global__ __launch_bounds__(256) void k_D(
    const float* __restrict__ wv, const float* __restrict__ bvv)
{
    int bh = blockIdx.y;
    int b  = bh >> 4, h = bh & 15;
    int m0 = blockIdx.x * 128;               // n-tile
    const float* A = g_c2 + (size_t)b*NL*P_;
    const float* W = wv   + (size_t)h*E_*P_;
    __shared__ float As[16][132], Ws[16][68];
    int t = threadIdx.x, tx = t & 15, ty = t >> 4;
    u64 acc[8][2] = {};
    for (int k0 = 0; k0 < P_; k0 += 16) {
#pragma unroll
        for (int i = 0; i < 2; i++) {
            int idx = t + i*256, row = idx >> 2, kq = (idx & 3)*4;
            float4 v = *(const float4*)&A[(size_t)(m0+row)*P_ + k0 + kq];
            As[kq+0][row]=v.x; As[kq+1][row]=v.y; As[kq+2][row]=v.z; As[kq+3][row]=v.w;
        }
        {
            int row = t >> 2, kq = (t & 3)*4;
            float4 v = *(const float4*)&W[(size_t)row*P_ + k0 + kq];
            Ws[kq+0][row]=v.x; Ws[kq+1][row]=v.y; Ws[kq+2][row]=v.z; Ws[kq+3][row]=v.w;
        }
        __syncthreads();
#pragma unroll
        for (int kk = 0; kk < 16; kk++) {
            float2 a01 = *(const float2*)&As[kk][ty*8 + 0];
            float2 a23 = *(const float2*)&As[kk][ty*8 + 2];
            float2 a45 = *(const float2*)&As[kk][ty*8 + 4];
            float2 a67 = *(const float2*)&As[kk][ty*8 + 6];
            float av[8] = {a01.x,a01.y,a23.x,a23.y,a45.x,a45.y,a67.x,a67.y};
            u64 bb[2];
            bb[0] = *(const u64*)&Ws[kk][tx*2 +  0];
            bb[1] = *(const u64*)&Ws[kk][tx*2 + 32];
#pragma unroll
            for (int i = 0; i < 8; i++) {
                u64 aa = pk2(av[i]);
                fma2(acc[i][0], aa, bb[0]);
                fma2(acc[i][1], aa, bb[1]);
            }
        }
        __syncthreads();
    }
#pragma unroll
    for (int i = 0; i < 8; i++) {
        int n = m0 + ty*8 + i;
#pragma unroll
        for (int j = 0; j < 2; j++) {
            int e = tx*2 + 32*j;
            float2 o = up2(acc[i][j]);
            o.x += bvv[((size_t)h*E_ + e+0)*NL + n];
            o.y += bvv[((size_t)h*E_ + e+1)*NL + n];
            *(float2*)&g_D[((size_t)bh*NL + n)*E_ + e] = o;
        }
    }
}

// ---------------- K1: scores = U[b] @ r[b]^T + pb + add ----------------
__global__ __launch_bounds__(256) void k_scores(
    const float* __restrict__ U, const float* __restrict__ pb,
    float* __restrict__ S)
{
    int b  = blockIdx.z;
    int m0 = blockIdx.x * 128, n0 = blockIdx.y * 128;
    const float* A  = U   + (size_t)b*8192*P_;
    const float* Bm = g_r + (size_t)b*NL*P_;
    __shared__ float As[16][132], Bs[16][132];
    int t = threadIdx.x, tx = t & 15, ty = t >> 4;
    u64 acc[8][4] = {};
    for (int k0 = 0; k0 < P_; k0 += 16) {
#pragma unroll
        for (int i = 0; i < 2; i++) {
            int idx = t + i*256, row = idx >> 2, kq = (idx & 3)*4;
            float4 v = *(const float4*)&A[(size_t)(m0+row)*P_ + k0 + kq];
            As[kq+0][row]=v.x; As[kq+1][row]=v.y; As[kq+2][row]=v.z; As[kq+3][row]=v.w;
        }
#pragma unroll
        for (int i = 0; i < 2; i++) {
            int idx = t + i*256, row = idx >> 2, kq = (idx & 3)*4;
            float4 v = *(const float4*)&Bm[(size_t)(n0+row)*P_ + k0 + kq];
            Bs[kq+0][row]=v.x; Bs[kq+1][row]=v.y; Bs[kq+2][row]=v.z; Bs[kq+3][row]=v.w;
        }
        __syncthreads();
#pragma unroll
        for (int kk = 0; kk < 16; kk++) {
            float2 a01 = *(const float2*)&As[kk][ty*8 + 0];
            float2 a23 = *(const float2*)&As[kk][ty*8 + 2];
            float2 a45 = *(const float2*)&As[kk][ty*8 + 4];
            float2 a67 = *(const float2*)&As[kk][ty*8 + 6];
            float av[8] = {a01.x,a01.y,a23.x,a23.y,a45.x,a45.y,a67.x,a67.y};
            u64 bb[4];
            bb[0] = *(const u64*)&Bs[kk][tx*2 +  0];
            bb[1] = *(const u64*)&Bs[kk][tx*2 + 32];
            bb[2] = *(const u64*)&Bs[kk][tx*2 + 64];
            bb[3] = *(const u64*)&Bs[kk][tx*2 + 96];
#pragma unroll
            for (int i = 0; i < 8; i++) {
                u64 aa = pk2(av[i]);
                fma2(acc[i][0], aa, bb[0]);
                fma2(acc[i][1], aa, bb[1]);
                fma2(acc[i][2], aa, bb[2]);
                fma2(acc[i][3], aa, bb[3]);
            }
        }
        __syncthreads();
    }
#pragma unroll
    for (int i = 0; i < 8; i++) {
        int gi = m0 + ty*8 + i;                     // row within b's 8192
        float pbv = pb[b*8192 + gi];
        const float* addp = g_add + ((size_t)(b*H_) + (gi >> 9))*NL + n0;
        float* op = S + ((size_t)(b*8192 + gi))*NL + n0;
#pragma unroll
        for (int j = 0; j < 4; j++) {
            int n = tx*2 + 32*j;
            float2 ad = *(const float2*)&addp[n];
            float2 r = up2(acc[i][j]);
            r.x += pbv + ad.x; r.y += pbv + ad.y;
            *(float2*)&op[n] = r;
        }
    }
}

// ---------------- softmax over last dim (512), in place ----------------
__global__ __launch_bounds__(128) void k_softmax(float* __restrict__ S)
{
    int row = blockIdx.x;
    float* p = S + (size_t)row * NL;
    int t = threadIdx.x;
    float x[4];
    float mx = -INFINITY;
#pragma unroll
    for (int i = 0; i < 4; i++) { x[i] = p[t + i*128]; mx = fmaxf(mx, x[i]); }
    __shared__ float smx[4], ssum[4];
#pragma unroll
    for (int o = 16; o > 0; o >>= 1) mx = fmaxf(mx, __shfl_xor_sync(0xffffffffu, mx, o));
    if ((t & 31) == 0) smx[t >> 5] = mx;
    __syncthreads();
    mx = fmaxf(fmaxf(smx[0], smx[1]), fmaxf(smx[2], smx[3]));
    float s = 0.f;
#pragma unroll
    for (int i = 0; i < 4; i++) { x[i] = expf(x[i] - mx); s += x[i]; }
#pragma unroll
    for (int o = 16; o > 0; o >>= 1) s += __shfl_xor_sync(0xffffffffu, s, o);
    if ((t & 31) == 0) ssum[t >> 5] = s;
    __syncthreads();
    s = ssum[0] + ssum[1] + ssum[2] + ssum[3];
    float inv = 1.0f / s;
#pragma unroll
    for (int i = 0; i < 4; i++) p[t + i*128] = x[i] * inv;
}

// ---------------- K2: G = (attn[b] @ c1[b]) * U  (NN gemm) ----------
__global__ __launch_bounds__(256) void k_av(
    const float* __restrict__ Attn, const float* __restrict__ U)
{
    int b  = blockIdx.z;
    int m0 = blockIdx.x * 128, n0 = blockIdx.y * 128;    // n over P
    const float* A  = Attn + (size_t)b*8192*NL;
    const float* Bm = g_c1 + (size_t)b*NL*P_;
    __shared__ float As[16][132], Bs[16][132];
    int t = threadIdx.x, tx = t & 15, ty = t >> 4;
    u64 acc[8][4] = {};
    for (int k0 = 0; k0 < NL; k0 += 16) {
#pragma unroll
        for (int i = 0; i < 2; i++) {
            int idx = t + i*256, row = idx >> 2, kq = (idx & 3)*4;
            float4 v = *(const float4*)&A[(size_t)(m0+row)*NL + k0 + kq];
            As[kq+0][row]=v.x; As[kq+1][row]=v.y; As[kq+2][row]=v.z; As[kq+3][row]=v.w;
        }
#pragma unroll
        for (int i = 0; i < 2; i++) {
            int idx = t + i*256, row = idx >> 5, c = (idx & 31)*4;
            float4 v = *(const float4*)&Bm[(size_t)(k0+row)*P_ + n0 + c];
            *(float4*)&Bs[row][c] = v;
        }
        __syncthreads();
#pragma unroll
        for (int kk = 0; kk < 16; kk++) {
            float2 a01 = *(const float2*)&As[kk][ty*8 + 0];
            float2 a23 = *(const float2*)&As[kk][ty*8 + 2];
            float2 a45 = *(const float2*)&As[kk][ty*8 + 4];
            float2 a67 = *(const float2*)&As[kk][ty*8 + 6];
            float av[8] = {a01.x,a01.y,a23.x,a23.y,a45.x,a45.y,a67.x,a67.y};
            u64 bb[4];
            bb[0] = *(const u64*)&Bs[kk][tx*2 +  0];
            bb[1] = *(const u64*)&Bs[kk][tx*2 + 32];
            bb[2] = *(const u64*)&Bs[kk][tx*2 + 64];
            bb[3] = *(const u64*)&Bs[kk][tx*2 + 96];
#pragma unroll
            for (int i = 0; i < 8; i++) {
                u64 aa = pk2(av[i]);
                fma2(acc[i][0], aa, bb[0]);
                fma2(acc[i][1], aa, bb[1]);
                fma2(acc[i][2], aa, bb[2]);
                fma2(acc[i][3], aa, bb[3]);
            }
        }
        __syncthreads();
    }
#pragma unroll
    for (int i = 0; i < 8; i++) {
        int gm = m0 + ty*8 + i;
        size_t rowoff = ((size_t)b*8192 + gm)*P_ + n0;
#pragma unroll
        for (int j = 0; j < 4; j++) {
            int n = tx*2 + 32*j;
            float2 u2 = *(const float2*)&U[rowoff + n];
            float2 g = up2(acc[i][j]);
            g.x *= u2.x; g.y *= u2.y;
            *(float2*)&g_G[rowoff + n] = g;
        }
    }
}

// ---------------- K3: out = G @ w_v^T + attn @ D  (tile 128 x 64) ----------------
__global__ __launch_bounds__(256) void k_out(
    const float* __restrict__ Attn, const float* __restrict__ wv,
    float* __restrict__ Out)
{
    int bh = blockIdx.y;
    int h  = bh & 15;
    int m0 = blockIdx.x * 128;
    const float* Gp = g_G  + (size_t)bh*NT*P_;
    const float* Ap = Attn + (size_t)bh*NT*NL;
    const float* W  = wv   + (size_t)h*E_*P_;
    const float* Dp = g_D  + (size_t)bh*NL*E_;
    __shared__ float As[16][132], Bs[16][68];
    int t = threadIdx.x, tx = t & 15, ty = t >> 4;
    u64 acc[8][2] = {};
    // phase 1: sum over P with w_v (NT)
    for (int k0 = 0; k0 < P_; k0 += 16) {
#pragma unroll
        for (int i = 0; i < 2; i++) {
            int idx = t + i*256, row = idx >> 2, kq = (idx & 3)*4;
            float4 v = *(const float4*)&Gp[(size_t)(m0+row)*P_ + k0 + kq];
            As[kq+0][row]=v.x; As[kq+1][row]=v.y; As[kq+2][row]=v.z; As[kq+3][row]=v.w;
        }
        {
            int row = t >> 2, kq = (t & 3)*4;
            float4 v = *(const float4*)&W[(size_t)row*P_ + k0 + kq];
            Bs[kq+0][row]=v.x; Bs[kq+1][row]=v.y; Bs[kq+2][row]=v.z; Bs[kq+3][row]=v.w;
        }
        __syncthreads();
#pragma unroll
        for (int kk = 0; kk < 16; kk++) {
            float2 a01 = *(const float2*)&As[kk][ty*8 + 0];
            float2 a23 = *(const float2*)&As[kk][ty*8 + 2];
            float2 a45 = *(const float2*)&As[kk][ty*8 + 4];
            float2 a67 = *(const float2*)&As[kk][ty*8 + 6];
            float av[8] = {a01.x,a01.y,a23.x,a23.y,a45.x,a45.y,a67.x,a67.y};
            u64 bb[2];
            bb[0] = *(const u64*)&Bs[kk][tx*2 +  0];
            bb[1] = *(const u64*)&Bs[kk][tx*2 + 32];
#pragma unroll
            for (int i = 0; i < 8; i++) {
                u64 aa = pk2(av[i]);
                fma2(acc[i][0], aa, bb[0]);
                fma2(acc[i][1], aa, bb[1]);
            }
        }
        __syncthreads();
    }
    // phase 2: sum over Nl with D (NN)
    for (int k0 = 0; k0 < NL; k0 += 16) {
#pragma unroll
        for (int i = 0; i < 2; i++) {
            int idx = t + i*256, row = idx >> 2, kq = (idx & 3)*4;
            float4 v = *(const float4*)&Ap[(size_t)(m0+row)*NL + k0 + kq];
            As[kq+0][row]=v.x; As[kq+1][row]=v.y; As[kq+2][row]=v.z; As[kq+3][row]=v.w;
        }
        {
            int row = t >> 4, c = (t & 15)*4;
            float4 v = *(const float4*)&Dp[(size_t)(k0+row)*E_ + c];
            *(float4*)&Bs[row][c] = v;
        }
        __syncthreads();
#pragma unroll
        for (int kk = 0; kk < 16; kk++) {
            float2 a01 = *(const float2*)&As[kk][ty*8 + 0];
            float2 a23 = *(const float2*)&As[kk][ty*8 + 2];
            float2 a45 = *(const float2*)&As[kk][ty*8 + 4];
            float2 a67 = *(const float2*)&As[kk][ty*8 + 6];
            float av[8] = {a01.x,a01.y,a23.x,a23.y,a45.x,a45.y,a67.x,a67.y};
            u64 bb[2];
            bb[0] = *(const u64*)&Bs[kk][tx*2 +  0];
            bb[1] = *(const u64*)&Bs[kk][tx*2 + 32];
#pragma unroll
            for (int i = 0; i < 8; i++) {
                u64 aa = pk2(av[i]);
                fma2(acc[i][0], aa, bb[0]);
                fma2(acc[i][1], aa, bb[1]);
            }
        }
        __syncthreads();
    }
#pragma unroll
    for (int i = 0; i < 8; i++) {
        int m = m0 + ty*8 + i;
#pragma unroll
        for (int j = 0; j < 2; j++) {
            int e = tx*2 + 32*j;
            float2 o = up2(acc[i][j]);
            *(float2*)&Out[((size_t)bh*NT + m)*E_ + e] = o;
        }
    }
}

// ---------------- launch ----------------
extern "C" void kernel_launch(void* const* d_in, const int* in_sizes, int n_in,
                              void* d_out, int out_size)
{
    const float* pu     = (const float*)d_in[0];  // [B,H,Nt,P]
    const float* pb     = (const float*)d_in[1];  // [B,H,Nt,1]
    const float* mu     = (const float*)d_in[2];  // [B,Nl,P]
    const float* logvar = (const float*)d_in[3];  // [B,Nl,P]
    const float* pi     = (const float*)d_in[4];  // [B,Nl,1]
    const float* wv     = (const float*)d_in[5];  // [H,E,P]
    const float* bvv    = (const float*)d_in[6];  // [H,E,Nl]
    const unsigned char* mask = (const unsigned char*)d_in[7]; // [B*H,1,Nl] bool

    float* out  = (float*)d_out;                  // [BH,Nt,E]
    float* attn = out + (size_t)BH*NT*E_;         // [BH,Nt,Nl]

    k_prep   <<<dim3(NL, B_),        256>>>(mu, logvar, pi, mask);
    k_D      <<<dim3(NL/128, BH),    256>>>(wv, bvv);
    k_scores <<<dim3(64, 4, B_),     256>>>(pu, pb, attn);
    k_softmax<<<BH*NT,               128>>>(attn);
    k_av     <<<dim3(64, 8, B_),     256>>>(attn, pu);
    k_out    <<<dim3(NT/128, BH),    256>>>(attn, wv, out);
}

// round 10
// speedup vs baseline: 2.7182x; 2.7182x over previous
#include <cuda_runtime.h>
#include <cuda_bf16.h>
#include <cuda_fp16.h>
#include <math.h>
#include <stdint.h>

#define B_  4
#define H_  16
#define NT  512
#define NL  512
#define E_  64
#define P_  1024
#define BH  (B_*H_)
#define PRIOR 8.0f

typedef unsigned int u32;

// ---------------- scratch (device globals) ----------------
__device__ __nv_bfloat16 g_Uh[(size_t)B_*8192*P_];  // U split hi  [b*8192+m][p]
__device__ __nv_bfloat16 g_Ul[(size_t)B_*8192*P_];  // U split lo
__device__ __nv_bfloat16 g_rh[B_*NL*P_];            // r = mu/bv hi [b][n][p]
__device__ __nv_bfloat16 g_rl[B_*NL*P_];            // r lo
__device__ __half        g_tf[B_*P_*NL];            // c1^T fp16 [b][p][n]
__device__ __half        g_Sf[(size_t)BH*NT*NL];    // attn fp16 [bh*Nt+m][n]
__device__ float g_c2 [B_*NL*P_];                   // 8*mu/bv
__device__ float g_add[BH*NL];
__device__ float g_D  [(size_t)BH*NL*E_];
__device__ float g_G  [(size_t)BH*NT*P_];

// ---------------- helpers ----------------
__device__ __forceinline__ u32 s2u(const void* p) {
    u32 a; asm("{ .reg .u64 t; cvta.to.shared.u64 t, %1; cvt.u32.u64 %0, t; }" : "=r"(a) : "l"(p));
    return a;
}
__device__ __forceinline__ void ldsm4(u32& r0, u32& r1, u32& r2, u32& r3, u32 a) {
    asm volatile("ldmatrix.sync.aligned.m8n8.x4.shared.b16 {%0,%1,%2,%3}, [%4];"
        : "=r"(r0), "=r"(r1), "=r"(r2), "=r"(r3) : "r"(a));
}
__device__ __forceinline__ void mma_bf16(float* c, const u32* a, const u32* b) {
    asm volatile("mma.sync.aligned.m16n8k16.row.col.f32.bf16.bf16.f32 "
        "{%0,%1,%2,%3}, {%4,%5,%6,%7}, {%8,%9}, {%0,%1,%2,%3};"
        : "+f"(c[0]), "+f"(c[1]), "+f"(c[2]), "+f"(c[3])
        : "r"(a[0]), "r"(a[1]), "r"(a[2]), "r"(a[3]), "r"(b[0]), "r"(b[1]));
}
__device__ __forceinline__ void mma_f16(float* c, const u32* a, const u32* b) {
    asm volatile("mma.sync.aligned.m16n8k16.row.col.f32.f16.f16.f32 "
        "{%0,%1,%2,%3}, {%4,%5,%6,%7}, {%8,%9}, {%0,%1,%2,%3};"
        : "+f"(c[0]), "+f"(c[1]), "+f"(c[2]), "+f"(c[3])
        : "r"(a[0]), "r"(a[1]), "r"(a[2]), "r"(a[3]), "r"(b[0]), "r"(b[1]));
}
__device__ __forceinline__ void splitbf(float x, __nv_bfloat16& h, __nv_bfloat16& l) {
    h = __float2bfloat16_rn(x);
    l = __float2bfloat16_rn(x - __bfloat162float(h));
}

#define SAS 72                        // padded smem stride (bf16/fp16 elems)
#define TILE_E (128*SAS)              // elems per tile buffer

// ---------------- K0: per-(b,n) precompute + splits + reductions ----------------
__global__ __launch_bounds__(256) void k_prep(
    const float* __restrict__ mu, const float* __restrict__ logvar,
    const float* __restrict__ pi, const unsigned char* __restrict__ mask)
{
    int n = blockIdx.x, b = blockIdx.y;
    int base = (b*NL + n)*P_;
    int t = threadIdx.x;
    float s2 = 0.f, s3 = 0.f;
#pragma unroll
    for (int i = 0; i < 4; i++) {
        int p = t + i*256;
        float m  = mu[base+p];
        float v  = expf(logvar[base+p]);
        float bv = v + PRIOR;
        float inv = 1.0f / bv;
        float r  = m * inv;
        float c1 = v * inv;
        g_c2[base+p] = PRIOR * m * inv;
        __nv_bfloat16 h, l;
        splitbf(r, h, l);
        g_rh[base+p] = h; g_rl[base+p] = l;
        g_tf[((size_t)b*P_ + p)*NL + n] = __float2half_rn(c1);
        s2 += m * m * inv;
        s3 += logf(bv);
    }
    __shared__ float red2[8], red3[8];
#pragma unroll
    for (int o = 16; o > 0; o >>= 1) {
        s2 += __shfl_down_sync(0xffffffffu, s2, o);
        s3 += __shfl_down_sync(0xffffffffu, s3, o);
    }
    if ((t & 31) == 0) { red2[t>>5] = s2; red3[t>>5] = s3; }
    __syncthreads();
    __shared__ float sbase;
    if (t == 0) {
        float a2 = 0.f, a3 = 0.f;
        for (int i = 0; i < 8; i++) { a2 += red2[i]; a3 += red3[i]; }
        float piv = pi[b*NL + n];
        float pc  = fmaxf(piv, 1.17549435e-38f);
        sbase = logf(pc) - 0.5f*a2 - 0.5f*a3;
    }
    __syncthreads();
    if (t < H_) {
        float piv = pi[b*NL + n];
        bool msk = (mask[(b*H_ + t)*NL + n] != 0) || (piv <= 0.f);
        g_add[(b*H_ + t)*NL + n] = msk ? -INFINITY : sbase;
    }
}

// ---------------- split U into bf16 hi/lo ----------------
__global__ __launch_bounds__(256) void k_split_U(const float* __restrict__ U)
{
    size_t i = ((size_t)blockIdx.x * 256 + threadIdx.x) * 4;
    float4 v = *(const float4*)(U + i);
    __nv_bfloat16 h[4], l[4];
    splitbf(v.x, h[0], l[0]); splitbf(v.y, h[1], l[1]);
    splitbf(v.z, h[2], l[2]); splitbf(v.w, h[3], l[3]);
    uint2 uh, ul;
    uh.x = ((u32)__bfloat16_as_ushort(h[1]) << 16) | __bfloat16_as_ushort(h[0]);
    uh.y = ((u32)__bfloat16_as_ushort(h[3]) << 16) | __bfloat16_as_ushort(h[2]);
    ul.x = ((u32)__bfloat16_as_ushort(l[1]) << 16) | __bfloat16_as_ushort(l[0]);
    ul.y = ((u32)__bfloat16_as_ushort(l[3]) << 16) | __bfloat16_as_ushort(l[2]);
    *(uint2*)&g_Uh[i] = uh;
    *(uint2*)&g_Ul[i] = ul;
}

// ---------------- K_D: D = c2 @ w_v^T + b_v^T  (scalar, 128x64) ----------------
__global__ __launch_bounds__(256) void k_D(
    const float* __restrict__ wv, const float* __restrict__ bvv)
{
    int bh = blockIdx.y;
    int b  = bh >> 4, h = bh & 15;
    int m0 = blockIdx.x * 128;
    const float* A = g_c2 + (size_t)b*NL*P_;
    const float* W = wv   + (size_t)h*E_*P_;
    __shared__ float As[16][132], Ws[16][68];
    int t = threadIdx.x, tx = t & 15, ty = t >> 4;
    float acc[8][4] = {};
    for (int k0 = 0; k0 < P_; k0 += 16) {
#pragma unroll
        for (int i = 0; i < 2; i++) {
            int idx = t + i*256, row = idx >> 2, kq = (idx & 3)*4;
            float4 v = *(const float4*)&A[(size_t)(m0+row)*P_ + k0 + kq];
            As[kq+0][row]=v.x; As[kq+1][row]=v.y; As[kq+2][row]=v.z; As[kq+3][row]=v.w;
        }
        {
            int row = t >> 2, kq = (t & 3)*4;
            float4 v = *(const float4*)&W[(size_t)row*P_ + k0 + kq];
            Ws[kq+0][row]=v.x; Ws[kq+1][row]=v.y; Ws[kq+2][row]=v.z; Ws[kq+3][row]=v.w;
        }
        __syncthreads();
#pragma unroll
        for (int kk = 0; kk < 16; kk++) {
            float a[8], w[4];
#pragma unroll
            for (int i = 0; i < 8; i++) a[i] = As[kk][ty*8 + i];
#pragma unroll
            for (int j = 0; j < 4; j++) w[j] = Ws[kk][tx*4 + j];
#pragma unroll
            for (int i = 0; i < 8; i++)
#pragma unroll
                for (int j = 0; j < 4; j++) acc[i][j] += a[i] * w[j];
        }
        __syncthreads();
    }
#pragma unroll
    for (int i = 0; i < 8; i++) {
        int n = m0 + ty*8 + i;
        float4 o;
        int e0 = tx*4;
        o.x = acc[i][0] + bvv[((size_t)h*E_ + e0+0)*NL + n];
        o.y = acc[i][1] + bvv[((size_t)h*E_ + e0+1)*NL + n];
        o.z = acc[i][2] + bvv[((size_t)h*E_ + e0+2)*NL + n];
        o.w = acc[i][3] + bvv[((size_t)h*E_ + e0+3)*NL + n];
        *(float4*)&g_D[((size_t)bh*NL + n)*E_ + e0] = o;
    }
}

// ---------------- K1: scores via mma.sync bf16 3-product ----------------
// tile 128(M) x 128(N), K chunks of 64; 8 warps in 2x4
__global__ __launch_bounds__(256, 1) void k_scores_mma(
    const float* __restrict__ pb, float* __restrict__ S)
{
    extern __shared__ char smraw[];
    __nv_bfloat16* sm = (__nv_bfloat16*)smraw;
    int t = threadIdx.x, lane = t & 31, wid = t >> 5;
    int wm = wid >> 2, wn = wid & 3;
    int n0 = blockIdx.x * 128, m0 = blockIdx.y * 128, b = blockIdx.z;

    const __nv_bfloat16* Ah = g_Uh + ((size_t)b*8192 + m0)*P_;
    const __nv_bfloat16* Al = g_Ul + ((size_t)b*8192 + m0)*P_;
    const __nv_bfloat16* Bh = g_rh + ((size_t)b*NL   + n0)*P_;
    const __nv_bfloat16* Bl = g_rl + ((size_t)b*NL   + n0)*P_;

    u32 uAh = s2u(sm);
    u32 uAl = uAh + TILE_E*2;
    u32 uBh = uAl + TILE_E*2;
    u32 uBl = uBh + TILE_E*2;

    int arow  = wm*64 + (lane & 15);
    int acolo = (lane >> 4) * 8;
    int brow  = wn*32 + (lane & 7) + ((lane >> 4) * 8);
    int bcolo = ((lane >> 3) & 1) * 8;

    float acc[4][4][4] = {};

    for (int c = 0; c < 16; c++) {
        int k0 = c * 64;
        __syncthreads();
#pragma unroll
        for (int i = 0; i < 4; i++) {
            int q = t + i*256;
            int row = q >> 3, cc = (q & 7) * 8;
            size_t so = (size_t)row * P_ + k0 + cc;
            int dst = row*SAS + cc;
            *(uint4*)&sm[0*TILE_E + dst] = *(const uint4*)&Ah[so];
            *(uint4*)&sm[1*TILE_E + dst] = *(const uint4*)&Al[so];
            *(uint4*)&sm[2*TILE_E + dst] = *(const uint4*)&Bh[so];
            *(uint4*)&sm[3*TILE_E + dst] = *(const uint4*)&Bl[so];
        }
        __syncthreads();
#pragma unroll
        for (int ks = 0; ks < 4; ks++) {
            int k = ks * 16;
            u32 aH[4][4], aL[4][4], bH[4][2], bL[4][2];
#pragma unroll
            for (int mt = 0; mt < 4; mt++) {
                u32 off = (u32)(((arow + mt*16)*SAS + k + acolo) * 2);
                ldsm4(aH[mt][0], aH[mt][1], aH[mt][2], aH[mt][3], uAh + off);
                ldsm4(aL[mt][0], aL[mt][1], aL[mt][2], aL[mt][3], uAl + off);
            }
#pragma unroll
            for (int pr = 0; pr < 2; pr++) {
                u32 off = (u32)(((brow + pr*16)*SAS + k + bcolo) * 2);
                ldsm4(bH[2*pr][0], bH[2*pr][1], bH[2*pr+1][0], bH[2*pr+1][1], uBh + off);
                ldsm4(bL[2*pr][0], bL[2*pr][1], bL[2*pr+1][0], bL[2*pr+1][1], uBl + off);
            }
#pragma unroll
            for (int mt = 0; mt < 4; mt++)
#pragma unroll
                for (int nt = 0; nt < 4; nt++) {
                    mma_bf16(acc[mt][nt], aH[mt], bH[nt]);
                    mma_bf16(acc[mt][nt], aH[mt], bL[nt]);
                    mma_bf16(acc[mt][nt], aL[mt], bH[nt]);
                }
        }
    }

    // epilogue: + pb + add, write fp32 scores
    int r = lane >> 2, c2_ = (lane & 3) * 2;
#pragma unroll
    for (int mt = 0; mt < 4; mt++) {
        int gm0 = m0 + wm*64 + mt*16 + r;
        int gm1 = gm0 + 8;
        float pb0 = pb[(size_t)b*8192 + gm0];
        float pb1 = pb[(size_t)b*8192 + gm1];
        const float* ad = g_add + ((size_t)(b*H_) + (gm0 >> 9))*NL;
        float* S0 = S + ((size_t)b*8192 + gm0)*NL;
        float* S1 = S + ((size_t)b*8192 + gm1)*NL;
#pragma unroll
        for (int nt = 0; nt < 4; nt++) {
            int gn = n0 + wn*32 + nt*8 + c2_;
            float2 a2 = *(const float2*)&ad[gn];
            float2 o0, o1;
            o0.x = acc[mt][nt][0] + pb0 + a2.x;
            o0.y = acc[mt][nt][1] + pb0 + a2.y;
            o1.x = acc[mt][nt][2] + pb1 + a2.x;
            o1.y = acc[mt][nt][3] + pb1 + a2.y;
            *(float2*)&S0[gn] = o0;
            *(float2*)&S1[gn] = o1;
        }
    }
}

// ---------------- softmax (512) in place + fp16 copy ----------------
__global__ __launch_bounds__(128) void k_softmax(float* __restrict__ S)
{
    int row = blockIdx.x;
    float* p = S + (size_t)row * NL;
    int t = threadIdx.x;
    float x[4];
    float mx = -INFINITY;
#pragma unroll
    for (int i = 0; i < 4; i++) { x[i] = p[t + i*128]; mx = fmaxf(mx, x[i]); }
    __shared__ float smx[4], ssum[4];
#pragma unroll
    for (int o = 16; o > 0; o >>= 1) mx = fmaxf(mx, __shfl_xor_sync(0xffffffffu, mx, o));
    if ((t & 31) == 0) smx[t >> 5] = mx;
    __syncthreads();
    mx = fmaxf(fmaxf(smx[0], smx[1]), fmaxf(smx[2], smx[3]));
    float s = 0.f;
#pragma unroll
    for (int i = 0; i < 4; i++) { x[i] = expf(x[i] - mx); s += x[i]; }
#pragma unroll
    for (int o = 16; o > 0; o >>= 1) s += __shfl_xor_sync(0xffffffffu, s, o);
    if ((t & 31) == 0) ssum[t >> 5] = s;
    __syncthreads();
    s = ssum[0] + ssum[1] + ssum[2] + ssum[3];
    float inv = 1.0f / s;
    size_t rb = (size_t)row * NL;
#pragma unroll
    for (int i = 0; i < 4; i++) {
        float y = x[i] * inv;
        p[t + i*128] = y;
        g_Sf[rb + t + i*128] = __float2half_rn(y);
    }
}

// ---------------- K2: G = (attn @ c1) * U via mma.sync fp16 ----------------
// tile 128(M) x 128(P), K = Nl = 512
__global__ __launch_bounds__(256, 1) void k_av_mma(const float* __restrict__ U)
{
    extern __shared__ char smraw[];
    __half* sm = (__half*)smraw;
    int t = threadIdx.x, lane = t & 31, wid = t >> 5;
    int wm = wid >> 2, wn = wid & 3;
    int p0 = blockIdx.x * 128, m0 = blockIdx.y * 128, b = blockIdx.z;

    const __half* A = g_Sf + ((size_t)b*8192 + m0)*NL;
    const __half* Bm = g_tf + ((size_t)b*P_  + p0)*NL;

    u32 uA = s2u(sm);
    u32 uB = uA + TILE_E*2;

    int arow  = wm*64 + (lane & 15);
    int acolo = (lane >> 4) * 8;
    int brow  = wn*32 + (lane & 7) + ((lane >> 4) * 8);
    int bcolo = ((lane >> 3) & 1) * 8;

    float acc[4][4][4] = {};

    for (int c = 0; c < 8; c++) {
        int k0 = c * 64;
        __syncthreads();
#pragma unroll
        for (int i = 0; i < 4; i++) {
            int q = t + i*256;
            int row = q >> 3, cc = (q & 7) * 8;
            size_t so = (size_t)row * NL + k0 + cc;
            int dst = row*SAS + cc;
            *(uint4*)&sm[0*TILE_E + dst] = *(const uint4*)&A[so];
            *(uint4*)&sm[1*TILE_E + dst] = *(const uint4*)&Bm[so];
        }
        __syncthreads();
#pragma unroll
        for (int ks = 0; ks < 4; ks++) {
            int k = ks * 16;
            u32 aF[4][4], bF[4][2];
#pragma unroll
            for (int mt = 0; mt < 4; mt++) {
                u32 off = (u32)(((arow + mt*16)*SAS + k + acolo) * 2);
                ldsm4(aF[mt][0], aF[mt][1], aF[mt][2], aF[mt][3], uA + off);
            }
#pragma unroll
            for (int pr = 0; pr < 2; pr++) {
                u32 off = (u32)(((brow + pr*16)*SAS + k + bcolo) * 2);
                ldsm4(bF[2*pr][0], bF[2*pr][1], bF[2*pr+1][0], bF[2*pr+1][1], uB + off);
            }
#pragma unroll
            for (int mt = 0; mt < 4; mt++)
#pragma unroll
                for (int nt = 0; nt < 4; nt++)
                    mma_f16(acc[mt][nt], aF[mt], bF[nt]);
        }
    }

    // epilogue: * U, write fp32 G
    int r = lane >> 2, c2_ = (lane & 3) * 2;
#pragma unroll
    for (int mt = 0; mt < 4; mt++) {
        int gm0 = m0 + wm*64 + mt*16 + r;
        size_t ro0 = ((size_t)b*8192 + gm0)*P_;
        size_t ro1 = ro0 + 8*(size_t)P_;
#pragma unroll
        for (int nt = 0; nt < 4; nt++) {
            int gp = p0 + wn*32 + nt*8 + c2_;
            float2 u0 = *(const float2*)&U[ro0 + gp];
            float2 u1 = *(const float2*)&U[ro1 + gp];
            float2 o0, o1;
            o0.x = acc[mt][nt][0] * u0.x;
            o0.y = acc[mt][nt][1] * u0.y;
            o1.x = acc[mt][nt][2] * u1.x;
            o1.y = acc[mt][nt][3] * u1.y;
            *(float2*)&g_G[ro0 + gp] = o0;
            *(float2*)&g_G[ro1 + gp] = o1;
        }
    }
}

// ---------------- K3: out = G @ w_v^T + attn @ D (scalar, 128x64) ----------------
__global__ __launch_bounds__(256) void k_out(
    const float* __restrict__ Attn, const float* __restrict__ wv,
    float* __restrict__ Out)
{
    int bh = blockIdx.y;
    int h  = bh & 15;
    int m0 = blockIdx.x * 128;
    const float* Gp = g_G  + (size_t)bh*NT*P_;
    const float* Ap = Attn + (size_t)bh*NT*NL;
    const float* W  = wv   + (size_t)h*E_*P_;
    const float* Dp = g_D  + (size_t)bh*NL*E_;
    __shared__ float As[16][132], Bs[16][68];
    int t = threadIdx.x, tx = t & 15, ty = t >> 4;
    float acc[8][4] = {};
    for (int k0 = 0; k0 < P_; k0 += 16) {
#pragma unroll
        for (int i = 0; i < 2; i++) {
            int idx = t + i*256, row = idx >> 2, kq = (idx & 3)*4;
            float4 v = *(const float4*)&Gp[(size_t)(m0+row)*P_ + k0 + kq];
            As[kq+0][row]=v.x; As[kq+1][row]=v.y; As[kq+2][row]=v.z; As[kq+3][row]=v.w;
        }
        {
            int row = t >> 2, kq = (t & 3)*4;
            float4 v = *(const float4*)&W[(size_t)row*P_ + k0 + kq];
            Bs[kq+0][row]=v.x; Bs[kq+1][row]=v.y; Bs[kq+2][row]=v.z; Bs[kq+3][row]=v.w;
        }
        __syncthreads();
#pragma unroll
        for (int kk = 0; kk < 16; kk++) {
            float a[8], w[4];
#pragma unroll
            for (int i = 0; i < 8; i++) a[i] = As[kk][ty*8 + i];
#pragma unroll
            for (int j = 0; j < 4; j++) w[j] = Bs[kk][tx*4 + j];
#pragma unroll
            for (int i = 0; i < 8; i++)
#pragma unroll
                for (int j = 0; j < 4; j++) acc[i][j] += a[i] * w[j];
        }
        __syncthreads();
    }
    for (int k0 = 0; k0 < NL; k0 += 16) {
#pragma unroll
        for (int i = 0; i < 2; i++) {
            int idx = t + i*256, row = idx >> 2, kq = (idx & 3)*4;
            float4 v = *(const float4*)&Ap[(size_t)(m0+row)*NL + k0 + kq];
            As[kq+0][row]=v.x; As[kq+1][row]=v.y; As[kq+2][row]=v.z; As[kq+3][row]=v.w;
        }
        {
            int row = t >> 4, c = (t & 15)*4;
            float4 v = *(const float4*)&Dp[(size_t)(k0+row)*E_ + c];
            *(float4*)&Bs[row][c] = v;
        }
        __syncthreads();
#pragma unroll
        for (int kk = 0; kk < 16; kk++) {
            float a[8], w[4];
#pragma unroll
            for (int i = 0; i < 8; i++) a[i] = As[kk][ty*8 + i];
#pragma unroll
            for (int j = 0; j < 4; j++) w[j] = Bs[kk][tx*4 + j];
#pragma unroll
            for (int i = 0; i < 8; i++)
#pragma unroll
                for (int j = 0; j < 4; j++) acc[i][j] += a[i] * w[j];
        }
        __syncthreads();
    }
#pragma unroll
    for (int i = 0; i < 8; i++) {
        int m = m0 + ty*8 + i;
        float4 o;
        o.x = acc[i][0]; o.y = acc[i][1]; o.z = acc[i][2]; o.w = acc[i][3];
        *(float4*)&Out[((size_t)bh*NT + m)*E_ + tx*4] = o;
    }
}

// ---------------- launch ----------------
extern "C" void kernel_launch(void* const* d_in, const int* in_sizes, int n_in,
                              void* d_out, int out_size)
{
    const float* pu     = (const float*)d_in[0];  // [B,H,Nt,P]
    const float* pb     = (const float*)d_in[1];  // [B,H,Nt,1]
    const float* mu     = (const float*)d_in[2];  // [B,Nl,P]
    const float* logvar = (const float*)d_in[3];  // [B,Nl,P]
    const float* pi     = (const float*)d_in[4];  // [B,Nl,1]
    const float* wv     = (const float*)d_in[5];  // [H,E,P]
    const float* bvv    = (const float*)d_in[6];  // [H,E,Nl]
    const unsigned char* mask = (const unsigned char*)d_in[7]; // [B*H,1,Nl]

    float* out  = (float*)d_out;                  // [BH,Nt,E]
    float* attn = out + (size_t)BH*NT*E_;         // [BH,Nt,Nl]

    const int SM_SCORES = 4 * TILE_E * 2;         // 73728 B
    const int SM_AV     = 2 * TILE_E * 2;         // 36864 B
    cudaFuncSetAttribute(k_scores_mma, cudaFuncAttributeMaxDynamicSharedMemorySize, SM_SCORES);
    cudaFuncSetAttribute(k_av_mma,     cudaFuncAttributeMaxDynamicSharedMemorySize, SM_AV);

    k_prep      <<<dim3(NL, B_),     256>>>(mu, logvar, pi, mask);
    k_split_U   <<<32768,            256>>>(pu);
    k_D         <<<dim3(NL/128, BH), 256>>>(wv, bvv);
    k_scores_mma<<<dim3(4, 64, B_),  256, SM_SCORES>>>(pb, attn);
    k_softmax   <<<BH*NT,            128>>>(attn);
    k_av_mma    <<<dim3(8, 64, B_),  256, SM_AV>>>(pu);
    k_out       <<<dim3(NT/128, BH), 256>>>(attn, wv, out);
}

// round 11
// speedup vs baseline: 3.2638x; 1.2007x over previous
#include <cuda_runtime.h>
#include <cuda_bf16.h>
#include <cuda_fp16.h>
#include <math.h>
#include <stdint.h>

#define B_  4
#define H_  16
#define NT  512
#define NL  512
#define E_  64
#define P_  1024
#define BH  (B_*H_)
#define PRIOR 8.0f

typedef unsigned int u32;

// ---------------- scratch (device globals) ----------------
__device__ __nv_bfloat16 g_Uh[(size_t)B_*8192*P_];  // U split hi  [b*8192+m][p]
__device__ __nv_bfloat16 g_Ul[(size_t)B_*8192*P_];
__device__ __nv_bfloat16 g_rh[B_*NL*P_];            // r = mu/bv hi [b][n][p]
__device__ __nv_bfloat16 g_rl[B_*NL*P_];
__device__ __half        g_tf[B_*P_*NL];            // c1^T fp16 [b][p][n]
__device__ __half        g_Sf[(size_t)BH*NT*NL];    // attn fp16 [bh*Nt+m][n]
__device__ __nv_bfloat16 g_Wh[H_*E_*P_];            // w_v split hi [h*E+e][p]
__device__ __nv_bfloat16 g_Wl[H_*E_*P_];
__device__ __nv_bfloat16 g_Gh[(size_t)BH*NT*P_];    // G split hi [bh*Nt+m][p]
__device__ __nv_bfloat16 g_Gl[(size_t)BH*NT*P_];
__device__ __half        g_Df[(size_t)BH*E_*NL];    // D^T fp16 [bh][e][n]
__device__ float g_c2 [B_*NL*P_];                   // 8*mu/bv
__device__ float g_add[BH*NL];

// ---------------- helpers ----------------
__device__ __forceinline__ u32 s2u(const void* p) {
    u32 a; asm("{ .reg .u64 t; cvta.to.shared.u64 t, %1; cvt.u32.u64 %0, t; }" : "=r"(a) : "l"(p));
    return a;
}
__device__ __forceinline__ void ldsm4(u32& r0, u32& r1, u32& r2, u32& r3, u32 a) {
    asm volatile("ldmatrix.sync.aligned.m8n8.x4.shared.b16 {%0,%1,%2,%3}, [%4];"
        : "=r"(r0), "=r"(r1), "=r"(r2), "=r"(r3) : "r"(a));
}
__device__ __forceinline__ void mma_bf16(float* c, const u32* a, const u32* b) {
    asm volatile("mma.sync.aligned.m16n8k16.row.col.f32.bf16.bf16.f32 "
        "{%0,%1,%2,%3}, {%4,%5,%6,%7}, {%8,%9}, {%0,%1,%2,%3};"
        : "+f"(c[0]), "+f"(c[1]), "+f"(c[2]), "+f"(c[3])
        : "r"(a[0]), "r"(a[1]), "r"(a[2]), "r"(a[3]), "r"(b[0]), "r"(b[1]));
}
__device__ __forceinline__ void mma_f16(float* c, const u32* a, const u32* b) {
    asm volatile("mma.sync.aligned.m16n8k16.row.col.f32.f16.f16.f32 "
        "{%0,%1,%2,%3}, {%4,%5,%6,%7}, {%8,%9}, {%0,%1,%2,%3};"
        : "+f"(c[0]), "+f"(c[1]), "+f"(c[2]), "+f"(c[3])
        : "r"(a[0]), "r"(a[1]), "r"(a[2]), "r"(a[3]), "r"(b[0]), "r"(b[1]));
}
__device__ __forceinline__ void splitbf(float x, __nv_bfloat16& h, __nv_bfloat16& l) {
    h = __float2bfloat16_rn(x);
    l = __float2bfloat16_rn(x - __bfloat162float(h));
}
#define CPA(s, g)   asm volatile("cp.async.cg.shared.global [%0], [%1], 16;" :: "r"(s), "l"(g) : "memory")
#define CP_COMMIT() asm volatile("cp.async.commit_group;" ::: "memory")
#define CP_WAIT(n)  asm volatile("cp.async.wait_group %0;" :: "n"(n) : "memory")

#define SAS     72                   // padded smem stride (elems)
#define TILE_E  (128*SAS)            // elems per 128-row tile
#define TILE_B  (TILE_E*2)           // bytes
#define HTILE_E (64*SAS)
#define HTILE_B (HTILE_E*2)

// ---------------- K0: per-(b,n) precompute + splits + reductions ----------------
__global__ __launch_bounds__(256) void k_prep(
    const float* __restrict__ mu, const float* __restrict__ logvar,
    const float* __restrict__ pi, const unsigned char* __restrict__ mask)
{
    int n = blockIdx.x, b = blockIdx.y;
    int base = (b*NL + n)*P_;
    int t = threadIdx.x;
    float s2 = 0.f, s3 = 0.f;
#pragma unroll
    for (int i = 0; i < 4; i++) {
        int p = t + i*256;
        float m  = mu[base+p];
        float v  = expf(logvar[base+p]);
        float bv = v + PRIOR;
        float inv = 1.0f / bv;
        float r  = m * inv;
        float c1 = v * inv;
        g_c2[base+p] = PRIOR * m * inv;
        __nv_bfloat16 h, l;
        splitbf(r, h, l);
        g_rh[base+p] = h; g_rl[base+p] = l;
        g_tf[((size_t)b*P_ + p)*NL + n] = __float2half_rn(c1);
        s2 += m * m * inv;
        s3 += logf(bv);
    }
    __shared__ float red2[8], red3[8];
#pragma unroll
    for (int o = 16; o > 0; o >>= 1) {
        s2 += __shfl_down_sync(0xffffffffu, s2, o);
        s3 += __shfl_down_sync(0xffffffffu, s3, o);
    }
    if ((t & 31) == 0) { red2[t>>5] = s2; red3[t>>5] = s3; }
    __syncthreads();
    __shared__ float sbase;
    if (t == 0) {
        float a2 = 0.f, a3 = 0.f;
        for (int i = 0; i < 8; i++) { a2 += red2[i]; a3 += red3[i]; }
        float piv = pi[b*NL + n];
        float pc  = fmaxf(piv, 1.17549435e-38f);
        sbase = logf(pc) - 0.5f*a2 - 0.5f*a3;
    }
    __syncthreads();
    if (t < H_) {
        float piv = pi[b*NL + n];
        bool msk = (mask[(b*H_ + t)*NL + n] != 0) || (piv <= 0.f);
        g_add[(b*H_ + t)*NL + n] = msk ? -INFINITY : sbase;
    }
}

// ---------------- generic fp32 -> bf16 hi/lo splitter ----------------
__global__ __launch_bounds__(256) void k_split(
    const float* __restrict__ X, __nv_bfloat16* __restrict__ Xh,
    __nv_bfloat16* __restrict__ Xl)
{
    size_t i = ((size_t)blockIdx.x * 256 + threadIdx.x) * 4;
    float4 v = *(const float4*)(X + i);
    __nv_bfloat16 h[4], l[4];
    splitbf(v.x, h[0], l[0]); splitbf(v.y, h[1], l[1]);
    splitbf(v.z, h[2], l[2]); splitbf(v.w, h[3], l[3]);
    uint2 uh, ul;
    uh.x = ((u32)__bfloat16_as_ushort(h[1]) << 16) | __bfloat16_as_ushort(h[0]);
    uh.y = ((u32)__bfloat16_as_ushort(h[3]) << 16) | __bfloat16_as_ushort(h[2]);
    ul.x = ((u32)__bfloat16_as_ushort(l[1]) << 16) | __bfloat16_as_ushort(l[0]);
    ul.y = ((u32)__bfloat16_as_ushort(l[3]) << 16) | __bfloat16_as_ushort(l[2]);
    *(uint2*)&Xh[i] = uh;
    *(uint2*)&Xl[i] = ul;
}

// ---------------- K_D: D^T[e][n] = (c2 @ w_v^T + b_v^T)^T, fp16 out ----------------
__global__ __launch_bounds__(256) void k_D(
    const float* __restrict__ wv, const float* __restrict__ bvv)
{
    int bh = blockIdx.y;
    int b  = bh >> 4, h = bh & 15;
    int m0 = blockIdx.x * 128;
    const float* A = g_c2 + (size_t)b*NL*P_;
    const float* W = wv   + (size_t)h*E_*P_;
    __shared__ float As[16][132], Ws[16][68];
    int t = threadIdx.x, tx = t & 15, ty = t >> 4;
    float acc[8][4] = {};
    for (int k0 = 0; k0 < P_; k0 += 16) {
#pragma unroll
        for (int i = 0; i < 2; i++) {
            int idx = t + i*256, row = idx >> 2, kq = (idx & 3)*4;
            float4 v = *(const float4*)&A[(size_t)(m0+row)*P_ + k0 + kq];
            As[kq+0][row]=v.x; As[kq+1][row]=v.y; As[kq+2][row]=v.z; As[kq+3][row]=v.w;
        }
        {
            int row = t >> 2, kq = (t & 3)*4;
            float4 v = *(const float4*)&W[(size_t)row*P_ + k0 + kq];
            Ws[kq+0][row]=v.x; Ws[kq+1][row]=v.y; Ws[kq+2][row]=v.z; Ws[kq+3][row]=v.w;
        }
        __syncthreads();
#pragma unroll
        for (int kk = 0; kk < 16; kk++) {
            float a[8], w[4];
#pragma unroll
            for (int i = 0; i < 8; i++) a[i] = As[kk][ty*8 + i];
#pragma unroll
            for (int j = 0; j < 4; j++) w[j] = Ws[kk][tx*4 + j];
#pragma unroll
            for (int i = 0; i < 8; i++)
#pragma unroll
                for (int j = 0; j < 4; j++) acc[i][j] += a[i] * w[j];
        }
        __syncthreads();
    }
#pragma unroll
    for (int i = 0; i < 8; i++) {
        int n = m0 + ty*8 + i;
#pragma unroll
        for (int j = 0; j < 4; j++) {
            int e = tx*4 + j;
            float val = acc[i][j] + bvv[((size_t)h*E_ + e)*NL + n];
            g_Df[((size_t)bh*E_ + e)*NL + n] = __float2half_rn(val);
        }
    }
}

// ---------------- K1: scores via mma.sync bf16 3-product, cp.async dbuf --------
__global__ __launch_bounds__(256, 1) void k_scores_mma(
    const float* __restrict__ pb, float* __restrict__ S)
{
    extern __shared__ char smraw[];
    u32 uSm = s2u(smraw);
    int t = threadIdx.x, lane = t & 31, wid = t >> 5;
    int wm = wid >> 2, wn = wid & 3;
    int n0 = blockIdx.x * 128, m0 = blockIdx.y * 128, b = blockIdx.z;

    const __nv_bfloat16* Ah = g_Uh + ((size_t)b*8192 + m0)*P_;
    const __nv_bfloat16* Al = g_Ul + ((size_t)b*8192 + m0)*P_;
    const __nv_bfloat16* Bh = g_rh + ((size_t)b*NL   + n0)*P_;
    const __nv_bfloat16* Bl = g_rl + ((size_t)b*NL   + n0)*P_;
    const u32 BUFB = 4*TILE_B;

    int arow  = wm*64 + (lane & 15);
    int acolo = (lane >> 4) * 8;
    int brow  = wn*32 + (lane & 7) + ((lane >> 4) * 8);
    int bcolo = ((lane >> 3) & 1) * 8;

    float acc[4][4][4] = {};

    // async chunk loader
    auto load_chunk = [&](int c, int buf) {
        u32 sbb = uSm + (u32)buf * BUFB;
        int k0 = c * 64;
#pragma unroll
        for (int i = 0; i < 4; i++) {
            int q = t + i*256;
            int row = q >> 3, cc = (q & 7) * 8;
            u32 doff = (u32)(row*SAS + cc) * 2;
            size_t so = (size_t)row * P_ + k0 + cc;
            CPA(sbb + 0*TILE_B + doff, Ah + so);
            CPA(sbb + 1*TILE_B + doff, Al + so);
            CPA(sbb + 2*TILE_B + doff, Bh + so);
            CPA(sbb + 3*TILE_B + doff, Bl + so);
        }
    };

    load_chunk(0, 0); CP_COMMIT();
    for (int c = 0; c < 16; c++) {
        if (c < 15) { load_chunk(c+1, (c+1)&1); CP_COMMIT(); CP_WAIT(1); }
        else        { CP_WAIT(0); }
        __syncthreads();
        u32 u0 = uSm + (u32)(c&1) * BUFB;
        u32 uAh = u0, uAl = u0 + TILE_B, uBh = u0 + 2*TILE_B, uBl = u0 + 3*TILE_B;
#pragma unroll
        for (int ks = 0; ks < 4; ks++) {
            int k = ks * 16;
            u32 aH[4][4], aL[4][4], bH[4][2], bL[4][2];
#pragma unroll
            for (int mt = 0; mt < 4; mt++) {
                u32 off = (u32)(((arow + mt*16)*SAS + k + acolo) * 2);
                ldsm4(aH[mt][0], aH[mt][1], aH[mt][2], aH[mt][3], uAh + off);
                ldsm4(aL[mt][0], aL[mt][1], aL[mt][2], aL[mt][3], uAl + off);
            }
#pragma unroll
            for (int pr = 0; pr < 2; pr++) {
                u32 off = (u32)(((brow + pr*16)*SAS + k + bcolo) * 2);
                ldsm4(bH[2*pr][0], bH[2*pr][1], bH[2*pr+1][0], bH[2*pr+1][1], uBh + off);
                ldsm4(bL[2*pr][0], bL[2*pr][1], bL[2*pr+1][0], bL[2*pr+1][1], uBl + off);
            }
#pragma unroll
            for (int mt = 0; mt < 4; mt++)
#pragma unroll
                for (int nt = 0; nt < 4; nt++) {
                    mma_bf16(acc[mt][nt], aH[mt], bH[nt]);
                    mma_bf16(acc[mt][nt], aH[mt], bL[nt]);
                    mma_bf16(acc[mt][nt], aL[mt], bH[nt]);
                }
        }
        __syncthreads();
    }

    int r = lane >> 2, c2_ = (lane & 3) * 2;
#pragma unroll
    for (int mt = 0; mt < 4; mt++) {
        int gm0 = m0 + wm*64 + mt*16 + r;
        int gm1 = gm0 + 8;
        float pb0 = pb[(size_t)b*8192 + gm0];
        float pb1 = pb[(size_t)b*8192 + gm1];
        const float* ad = g_add + ((size_t)(b*H_) + (gm0 >> 9))*NL;
        float* S0 = S + ((size_t)b*8192 + gm0)*NL;
        float* S1 = S + ((size_t)b*8192 + gm1)*NL;
#pragma unroll
        for (int nt = 0; nt < 4; nt++) {
            int gn = n0 + wn*32 + nt*8 + c2_;
            float2 a2 = *(const float2*)&ad[gn];
            float2 o0, o1;
            o0.x = acc[mt][nt][0] + pb0 + a2.x;
            o0.y = acc[mt][nt][1] + pb0 + a2.y;
            o1.x = acc[mt][nt][2] + pb1 + a2.x;
            o1.y = acc[mt][nt][3] + pb1 + a2.y;
            *(float2*)&S0[gn] = o0;
            *(float2*)&S1[gn] = o1;
        }
    }
}

// ---------------- softmax (512) in place + fp16 copy ----------------
__global__ __launch_bounds__(128) void k_softmax(float* __restrict__ S)
{
    int row = blockIdx.x;
    float* p = S + (size_t)row * NL;
    int t = threadIdx.x;
    float x[4];
    float mx = -INFINITY;
#pragma unroll
    for (int i = 0; i < 4; i++) { x[i] = p[t + i*128]; mx = fmaxf(mx, x[i]); }
    __shared__ float smx[4], ssum[4];
#pragma unroll
    for (int o = 16; o > 0; o >>= 1) mx = fmaxf(mx, __shfl_xor_sync(0xffffffffu, mx, o));
    if ((t & 31) == 0) smx[t >> 5] = mx;
    __syncthreads();
    mx = fmaxf(fmaxf(smx[0], smx[1]), fmaxf(smx[2], smx[3]));
    float s = 0.f;
#pragma unroll
    for (int i = 0; i < 4; i++) { x[i] = expf(x[i] - mx); s += x[i]; }
#pragma unroll
    for (int o = 16; o > 0; o >>= 1) s += __shfl_xor_sync(0xffffffffu, s, o);
    if ((t & 31) == 0) ssum[t >> 5] = s;
    __syncthreads();
    s = ssum[0] + ssum[1] + ssum[2] + ssum[3];
    float inv = 1.0f / s;
    size_t rb = (size_t)row * NL;
#pragma unroll
    for (int i = 0; i < 4; i++) {
        float y = x[i] * inv;
        p[t + i*128] = y;
        g_Sf[rb + t + i*128] = __float2half_rn(y);
    }
}

// ---------------- K2: G = (attn @ c1) * U  (fp16 mma, cp.async dbuf) ------------
// writes G as bf16 hi/lo splits
__global__ __launch_bounds__(256, 1) void k_av_mma(const float* __restrict__ U)
{
    extern __shared__ char smraw[];
    u32 uSm = s2u(smraw);
    int t = threadIdx.x, lane = t & 31, wid = t >> 5;
    int wm = wid >> 2, wn = wid & 3;
    int p0 = blockIdx.x * 128, m0 = blockIdx.y * 128, b = blockIdx.z;

    const __half* A  = g_Sf + ((size_t)b*8192 + m0)*NL;
    const __half* Bm = g_tf + ((size_t)b*P_  + p0)*NL;
    const u32 BUFB = 2*TILE_B;

    int arow  = wm*64 + (lane & 15);
    int acolo = (lane >> 4) * 8;
    int brow  = wn*32 + (lane & 7) + ((lane >> 4) * 8);
    int bcolo = ((lane >> 3) & 1) * 8;

    float acc[4][4][4] = {};

    auto load_chunk = [&](int c, int buf) {
        u32 sbb = uSm + (u32)buf * BUFB;
        int k0 = c * 64;
#pragma unroll
        for (int i = 0; i < 4; i++) {
            int q = t + i*256;
            int row = q >> 3, cc = (q & 7) * 8;
            u32 doff = (u32)(row*SAS + cc) * 2;
            size_t so = (size_t)row * NL + k0 + cc;
            CPA(sbb + 0*TILE_B + doff, A  + so);
            CPA(sbb + 1*TILE_B + doff, Bm + so);
        }
    };

    load_chunk(0, 0); CP_COMMIT();
    for (int c = 0; c < 8; c++) {
        if (c < 7) { load_chunk(c+1, (c+1)&1); CP_COMMIT(); CP_WAIT(1); }
        else       { CP_WAIT(0); }
        __syncthreads();
        u32 u0 = uSm + (u32)(c&1) * BUFB;
        u32 uA = u0, uB = u0 + TILE_B;
#pragma unroll
        for (int ks = 0; ks < 4; ks++) {
            int k = ks * 16;
            u32 aF[4][4], bF[4][2];
#pragma unroll
            for (int mt = 0; mt < 4; mt++) {
                u32 off = (u32)(((arow + mt*16)*SAS + k + acolo) * 2);
                ldsm4(aF[mt][0], aF[mt][1], aF[mt][2], aF[mt][3], uA + off);
            }
#pragma unroll
            for (int pr = 0; pr < 2; pr++) {
                u32 off = (u32)(((brow + pr*16)*SAS + k + bcolo) * 2);
                ldsm4(bF[2*pr][0], bF[2*pr][1], bF[2*pr+1][0], bF[2*pr+1][1], uB + off);
            }
#pragma unroll
            for (int mt = 0; mt < 4; mt++)
#pragma unroll
                for (int nt = 0; nt < 4; nt++)
                    mma_f16(acc[mt][nt], aF[mt], bF[nt]);
        }
        __syncthreads();
    }

    int r = lane >> 2, c2_ = (lane & 3) * 2;
#pragma unroll
    for (int mt = 0; mt < 4; mt++) {
        int gm0 = m0 + wm*64 + mt*16 + r;
        size_t ro0 = ((size_t)b*8192 + gm0)*P_;
        size_t ro1 = ro0 + 8*(size_t)P_;
#pragma unroll
        for (int nt = 0; nt < 4; nt++) {
            int gp = p0 + wn*32 + nt*8 + c2_;
            float2 u0 = *(const float2*)&U[ro0 + gp];
            float2 u1 = *(const float2*)&U[ro1 + gp];
            float gx, gy;
            __nv_bfloat16 h0, l0, h1, l1;
            gx = acc[mt][nt][0] * u0.x; gy = acc[mt][nt][1] * u0.y;
            splitbf(gx, h0, l0); splitbf(gy, h1, l1);
            *(__nv_bfloat162*)&g_Gh[ro0 + gp] = __nv_bfloat162(h0, h1);
            *(__nv_bfloat162*)&g_Gl[ro0 + gp] = __nv_bfloat162(l0, l1);
            gx = acc[mt][nt][2] * u1.x; gy = acc[mt][nt][3] * u1.y;
            splitbf(gx, h0, l0); splitbf(gy, h1, l1);
            *(__nv_bfloat162*)&g_Gh[ro1 + gp] = __nv_bfloat162(h0, h1);
            *(__nv_bfloat162*)&g_Gl[ro1 + gp] = __nv_bfloat162(l0, l1);
        }
    }
}

// ---------------- K3: out = G @ w_v^T + attn @ D  (tensorized, 128x64) ----------
// phase1: bf16 3-product over K=P; phase2: fp16 over K=Nl
__global__ __launch_bounds__(256, 1) void k_out_mma(float* __restrict__ Out)
{
    extern __shared__ char smraw[];
    u32 uSm = s2u(smraw);
    int t = threadIdx.x, lane = t & 31, wid = t >> 5;
    int wm = wid >> 1, wn = wid & 1;             // 4 x 2 warps: M=32, N=32 each
    int bh = blockIdx.y, h = bh & 15;
    int m0 = blockIdx.x * 128;

    const __nv_bfloat16* GhP = g_Gh + ((size_t)bh*NT + m0)*P_;
    const __nv_bfloat16* GlP = g_Gl + ((size_t)bh*NT + m0)*P_;
    const __nv_bfloat16* WhP = g_Wh + (size_t)h*E_*P_;
    const __nv_bfloat16* WlP = g_Wl + (size_t)h*E_*P_;
    const __half*        Sp  = g_Sf + ((size_t)bh*NT + m0)*NL;
    const __half*        Dp  = g_Df + (size_t)bh*E_*NL;

    int arow  = wm*32 + (lane & 15);
    int acolo = (lane >> 4) * 8;
    int brow  = wn*32 + (lane & 7) + ((lane >> 4) * 8);
    int bcolo = ((lane >> 3) & 1) * 8;

    float acc[2][4][4] = {};

    // ---- phase 1: G @ W^T, K = 1024, bf16 3-product, single-buffered ----
    u32 uGh = uSm, uGl = uGh + TILE_B, uWh = uGl + TILE_B, uWl = uWh + HTILE_B;
    for (int c = 0; c < 16; c++) {
        int k0 = c * 64;
        __syncthreads();
#pragma unroll
        for (int i = 0; i < 4; i++) {                 // G tiles: 128 rows
            int q = t + i*256;
            int row = q >> 3, cc = (q & 7) * 8;
            u32 doff = (u32)(row*SAS + cc) * 2;
            size_t so = (size_t)row * P_ + k0 + cc;
            CPA(uGh + doff, GhP + so);
            CPA(uGl + doff, GlP + so);
        }
#pragma unroll
        for (int i = 0; i < 2; i++) {                 // W tiles: 64 rows
            int q = t + i*256;
            int row = q >> 3, cc = (q & 7) * 8;
            u32 doff = (u32)(row*SAS + cc) * 2;
            size_t so = (size_t)row * P_ + k0 + cc;
            CPA(uWh + doff, WhP + so);
            CPA(uWl + doff, WlP + so);
        }
        CP_COMMIT(); CP_WAIT(0);
        __syncthreads();
#pragma unroll
        for (int ks = 0; ks < 4; ks++) {
            int k = ks * 16;
            u32 aH[2][4], aL[2][4], bH[4][2], bL[4][2];
#pragma unroll
            for (int mt = 0; mt < 2; mt++) {
                u32 off = (u32)(((arow + mt*16)*SAS + k + acolo) * 2);
                ldsm4(aH[mt][0], aH[mt][1], aH[mt][2], aH[mt][3], uGh + off);
                ldsm4(aL[mt][0], aL[mt][1], aL[mt][2], aL[mt][3], uGl + off);
            }
#pragma unroll
            for (int pr = 0; pr < 2; pr++) {
                u32 off = (u32)(((brow + pr*16)*SAS + k + bcolo) * 2);
                ldsm4(bH[2*pr][0], bH[2*pr][1], bH[2*pr+1][0], bH[2*pr+1][1], uWh + off);
                ldsm4(bL[2*pr][0], bL[2*pr][1], bL[2*pr+1][0], bL[2*pr+1][1], uWl + off);
            }
#pragma unroll
            for (int mt = 0; mt < 2; mt++)
#pragma unroll
                for (int nt = 0; nt < 4; nt++) {
                    mma_bf16(acc[mt][nt], aH[mt], bH[nt]);
                    mma_bf16(acc[mt][nt], aH[mt], bL[nt]);
                    mma_bf16(acc[mt][nt], aL[mt], bH[nt]);
                }
        }
    }

    // ---- phase 2: attn @ D^T, K = 512, fp16 ----
    u32 uA = uSm, uD = uA + TILE_B;
    for (int c = 0; c < 8; c++) {
        int k0 = c * 64;
        __syncthreads();
#pragma unroll
        for (int i = 0; i < 4; i++) {                 // attn tile: 128 rows
            int q = t + i*256;
            int row = q >> 3, cc = (q & 7) * 8;
            u32 doff = (u32)(row*SAS + cc) * 2;
            CPA(uA + doff, Sp + (size_t)row * NL + k0 + cc);
        }
#pragma unroll
        for (int i = 0; i < 2; i++) {                 // D tile: 64 rows
            int q = t + i*256;
            int row = q >> 3, cc = (q & 7) * 8;
            u32 doff = (u32)(row*SAS + cc) * 2;
            CPA(uD + doff, Dp + (size_t)row * NL + k0 + cc);
        }
        CP_COMMIT(); CP_WAIT(0);
        __syncthreads();
#pragma unroll
        for (int ks = 0; ks < 4; ks++) {
            int k = ks * 16;
            u32 aF[2][4], bF[4][2];
#pragma unroll
            for (int mt = 0; mt < 2; mt++) {
                u32 off = (u32)(((arow + mt*16)*SAS + k + acolo) * 2);
                ldsm4(aF[mt][0], aF[mt][1], aF[mt][2], aF[mt][3], uA + off);
            }
#pragma unroll
            for (int pr = 0; pr < 2; pr++) {
                u32 off = (u32)(((brow + pr*16)*SAS + k + bcolo) * 2);
                ldsm4(bF[2*pr][0], bF[2*pr][1], bF[2*pr+1][0], bF[2*pr+1][1], uD + off);
            }
#pragma unroll
            for (int mt = 0; mt < 2; mt++)
#pragma unroll
                for (int nt = 0; nt < 4; nt++)
                    mma_f16(acc[mt][nt], aF[mt], bF[nt]);
        }
    }

    int r = lane >> 2, c2_ = (lane & 3) * 2;
#pragma unroll
    for (int mt = 0; mt < 2; mt++) {
        int gm0 = m0 + wm*32 + mt*16 + r;
        float* O0 = Out + ((size_t)bh*NT + gm0)*E_;
        float* O1 = O0 + 8*(size_t)E_;
#pragma unroll
        for (int nt = 0; nt < 4; nt++) {
            int ge = wn*32 + nt*8 + c2_;
            float2 o0, o1;
            o0.x = acc[mt][nt][0]; o0.y = acc[mt][nt][1];
            o1.x = acc[mt][nt][2]; o1.y = acc[mt][nt][3];
            *(float2*)&O0[ge] = o0;
            *(float2*)&O1[ge] = o1;
        }
    }
}

// ---------------- launch ----------------
extern "C" void kernel_launch(void* const* d_in, const int* in_sizes, int n_in,
                              void* d_out, int out_size)
{
    const float* pu     = (const float*)d_in[0];  // [B,H,Nt,P]
    const float* pb     = (const float*)d_in[1];  // [B,H,Nt,1]
    const float* mu     = (const float*)d_in[2];  // [B,Nl,P]
    const float* logvar = (const float*)d_in[3];  // [B,Nl,P]
    const float* pi     = (const float*)d_in[4];  // [B,Nl,1]
    const float* wv     = (const float*)d_in[5];  // [H,E,P]
    const float* bvv    = (const float*)d_in[6];  // [H,E,Nl]
    const unsigned char* mask = (const unsigned char*)d_in[7]; // [B*H,1,Nl]

    float* out  = (float*)d_out;                  // [BH,Nt,E]
    float* attn = out + (size_t)BH*NT*E_;         // [BH,Nt,Nl]

    __nv_bfloat16 *Uh, *Ul, *Wh, *Wl;
    cudaGetSymbolAddress((void**)&Uh, g_Uh);
    cudaGetSymbolAddress((void**)&Ul, g_Ul);
    cudaGetSymbolAddress((void**)&Wh, g_Wh);
    cudaGetSymbolAddress((void**)&Wl, g_Wl);

    const int SM_SCORES = 2 * 4 * TILE_B;         // 147456 B (double buffer)
    const int SM_AV     = 2 * 2 * TILE_B;         // 73728 B
    const int SM_OUT    = 2 * TILE_B + 2 * HTILE_B; // 55296 B
    cudaFuncSetAttribute(k_scores_mma, cudaFuncAttributeMaxDynamicSharedMemorySize, SM_SCORES);
    cudaFuncSetAttribute(k_av_mma,     cudaFuncAttributeMaxDynamicSharedMemorySize, SM_AV);
    cudaFuncSetAttribute(k_out_mma,    cudaFuncAttributeMaxDynamicSharedMemorySize, SM_OUT);

    k_prep      <<<dim3(NL, B_),     256>>>(mu, logvar, pi, mask);
    k_split     <<<32768,            256>>>(pu, Uh, Ul);
    k_split     <<<1024,             256>>>(wv, Wh, Wl);
    k_D         <<<dim3(NL/128, BH), 256>>>(wv, bvv);
    k_scores_mma<<<dim3(4, 64, B_),  256, SM_SCORES>>>(pb, attn);
    k_softmax   <<<BH*NT,            128>>>(attn);
    k_av_mma    <<<dim3(8, 64, B_),  256, SM_AV>>>(pu);
    k_out_mma   <<<dim3(NT/128, BH), 256, SM_OUT>>>(out);
}

// round 12
// speedup vs baseline: 3.6881x; 1.1300x over previous
#include <cuda_runtime.h>
#include <cuda_bf16.h>
#include <cuda_fp16.h>
#include <math.h>
#include <stdint.h>

#define B_  4
#define H_  16
#define NT  512
#define NL  512
#define E_  64
#define P_  1024
#define BH  (B_*H_)
#define PRIOR 8.0f

typedef unsigned int u32;

// ---------------- scratch (device globals) ----------------
__device__ __nv_bfloat16 g_Uh[(size_t)B_*8192*P_];  // U split hi  [b*8192+m][p]
__device__ __nv_bfloat16 g_Ul[(size_t)B_*8192*P_];
__device__ __nv_bfloat16 g_rh[B_*NL*P_];            // r = mu/bv hi [b][n][p]
__device__ __nv_bfloat16 g_rl[B_*NL*P_];
__device__ __half        g_tf[B_*P_*NL];            // c1^T fp16 [b][p][n]
__device__ __half        g_Sf[(size_t)BH*NT*NL];    // attn fp16 [bh*Nt+m][n]
__device__ __nv_bfloat16 g_Wh[H_*E_*P_];            // w_v split hi [h*E+e][p]
__device__ __nv_bfloat16 g_Wl[H_*E_*P_];
__device__ __nv_bfloat16 g_Gh[(size_t)BH*NT*P_];    // G split hi [bh*Nt+m][p]
__device__ __nv_bfloat16 g_Gl[(size_t)BH*NT*P_];
__device__ __half        g_Df[(size_t)BH*E_*NL];    // D^T fp16 [bh][e][n]
__device__ float g_add[BH*NL];

// ---------------- helpers ----------------
__device__ __forceinline__ u32 s2u(const void* p) {
    u32 a; asm("{ .reg .u64 t; cvta.to.shared.u64 t, %1; cvt.u32.u64 %0, t; }" : "=r"(a) : "l"(p));
    return a;
}
__device__ __forceinline__ void ldsm4(u32& r0, u32& r1, u32& r2, u32& r3, u32 a) {
    asm volatile("ldmatrix.sync.aligned.m8n8.x4.shared.b16 {%0,%1,%2,%3}, [%4];"
        : "=r"(r0), "=r"(r1), "=r"(r2), "=r"(r3) : "r"(a));
}
__device__ __forceinline__ void mma_bf16(float* c, const u32* a, const u32* b) {
    asm volatile("mma.sync.aligned.m16n8k16.row.col.f32.bf16.bf16.f32 "
        "{%0,%1,%2,%3}, {%4,%5,%6,%7}, {%8,%9}, {%0,%1,%2,%3};"
        : "+f"(c[0]), "+f"(c[1]), "+f"(c[2]), "+f"(c[3])
        : "r"(a[0]), "r"(a[1]), "r"(a[2]), "r"(a[3]), "r"(b[0]), "r"(b[1]));
}
__device__ __forceinline__ void mma_f16(float* c, const u32* a, const u32* b) {
    asm volatile("mma.sync.aligned.m16n8k16.row.col.f32.f16.f16.f32 "
        "{%0,%1,%2,%3}, {%4,%5,%6,%7}, {%8,%9}, {%0,%1,%2,%3};"
        : "+f"(c[0]), "+f"(c[1]), "+f"(c[2]), "+f"(c[3])
        : "r"(a[0]), "r"(a[1]), "r"(a[2]), "r"(a[3]), "r"(b[0]), "r"(b[1]));
}
__device__ __forceinline__ void splitbf(float x, __nv_bfloat16& h, __nv_bfloat16& l) {
    h = __float2bfloat16_rn(x);
    l = __float2bfloat16_rn(x - __bfloat162float(h));
}
#define CPA(s, g)   asm volatile("cp.async.cg.shared.global [%0], [%1], 16;" :: "r"(s), "l"(g) : "memory")
#define CP_COMMIT() asm volatile("cp.async.commit_group;" ::: "memory")
#define CP_WAIT(n)  asm volatile("cp.async.wait_group %0;" :: "n"(n) : "memory")

#define SAS     72                   // padded smem stride (elems)
#define TILE_E  (128*SAS)            // elems per 128-row tile
#define TILE_B  (TILE_E*2)           // bytes
#define HTILE_E (64*SAS)
#define HTILE_B (HTILE_E*2)

// ---------------- K0: per-(b,n) precompute + splits + reductions ----------------
__global__ __launch_bounds__(256) void k_prep(
    const float* __restrict__ mu, const float* __restrict__ logvar,
    const float* __restrict__ pi, const unsigned char* __restrict__ mask)
{
    int n = blockIdx.x, b = blockIdx.y;
    int base = (b*NL + n)*P_;
    int t = threadIdx.x;
    float s2 = 0.f, s3 = 0.f;
#pragma unroll
    for (int i = 0; i < 4; i++) {
        int p = t + i*256;
        float m  = mu[base+p];
        float v  = expf(logvar[base+p]);
        float bv = v + PRIOR;
        float inv = 1.0f / bv;
        float r  = m * inv;
        float c1 = v * inv;
        __nv_bfloat16 h, l;
        splitbf(r, h, l);
        g_rh[base+p] = h; g_rl[base+p] = l;
        g_tf[((size_t)b*P_ + p)*NL + n] = __float2half_rn(c1);
        s2 += m * m * inv;
        s3 += logf(bv);
    }
    __shared__ float red2[8], red3[8];
#pragma unroll
    for (int o = 16; o > 0; o >>= 1) {
        s2 += __shfl_down_sync(0xffffffffu, s2, o);
        s3 += __shfl_down_sync(0xffffffffu, s3, o);
    }
    if ((t & 31) == 0) { red2[t>>5] = s2; red3[t>>5] = s3; }
    __syncthreads();
    __shared__ float sbase;
    if (t == 0) {
        float a2 = 0.f, a3 = 0.f;
        for (int i = 0; i < 8; i++) { a2 += red2[i]; a3 += red3[i]; }
        float piv = pi[b*NL + n];
        float pc  = fmaxf(piv, 1.17549435e-38f);
        sbase = logf(pc) - 0.5f*a2 - 0.5f*a3;
    }
    __syncthreads();
    if (t < H_) {
        float piv = pi[b*NL + n];
        bool msk = (mask[(b*H_ + t)*NL + n] != 0) || (piv <= 0.f);
        g_add[(b*H_ + t)*NL + n] = msk ? -INFINITY : sbase;
    }
}

// ---------------- generic fp32 -> bf16 hi/lo splitter ----------------
__global__ __launch_bounds__(256) void k_split(
    const float* __restrict__ X, __nv_bfloat16* __restrict__ Xh,
    __nv_bfloat16* __restrict__ Xl)
{
    size_t i = ((size_t)blockIdx.x * 256 + threadIdx.x) * 4;
    float4 v = *(const float4*)(X + i);
    __nv_bfloat16 h[4], l[4];
    splitbf(v.x, h[0], l[0]); splitbf(v.y, h[1], l[1]);
    splitbf(v.z, h[2], l[2]); splitbf(v.w, h[3], l[3]);
    uint2 uh, ul;
    uh.x = ((u32)__bfloat16_as_ushort(h[1]) << 16) | __bfloat16_as_ushort(h[0]);
    uh.y = ((u32)__bfloat16_as_ushort(h[3]) << 16) | __bfloat16_as_ushort(h[2]);
    ul.x = ((u32)__bfloat16_as_ushort(l[1]) << 16) | __bfloat16_as_ushort(l[0]);
    ul.y = ((u32)__bfloat16_as_ushort(l[3]) << 16) | __bfloat16_as_ushort(l[2]);
    *(uint2*)&Xh[i] = uh;
    *(uint2*)&Xl[i] = ul;
}

// ---------------- K_D: D^T[e][n] = 8*(r @ w_v^T) + b_v^T via bf16 mma ----------
// reuses g_rh/g_rl and g_Wh/g_Wl splits. tile: 128(n) x 64(e), K = P = 1024
__global__ __launch_bounds__(256, 1) void k_D_mma(const float* __restrict__ bvv)
{
    extern __shared__ char smraw[];
    u32 uSm = s2u(smraw);
    int t = threadIdx.x, lane = t & 31, wid = t >> 5;
    int wm = wid >> 1, wn = wid & 1;             // 4 x 2 warps: 32(M) x 32(N) each
    int bh = blockIdx.y, b = bh >> 4, h = bh & 15;
    int m0 = blockIdx.x * 128;                   // n-tile

    const __nv_bfloat16* Ah = g_rh + ((size_t)b*NL + m0)*P_;
    const __nv_bfloat16* Al = g_rl + ((size_t)b*NL + m0)*P_;
    const __nv_bfloat16* WhP = g_Wh + (size_t)h*E_*P_;
    const __nv_bfloat16* WlP = g_Wl + (size_t)h*E_*P_;

    int arow  = wm*32 + (lane & 15);
    int acolo = (lane >> 4) * 8;
    int brow  = wn*32 + (lane & 7) + ((lane >> 4) * 8);
    int bcolo = ((lane >> 3) & 1) * 8;

    float acc[2][4][4] = {};

    u32 uAh = uSm, uAl = uAh + TILE_B, uWh = uAl + TILE_B, uWl = uWh + HTILE_B;
    for (int c = 0; c < 16; c++) {
        int k0 = c * 64;
        __syncthreads();
#pragma unroll
        for (int i = 0; i < 4; i++) {                 // A tiles: 128 rows
            int q = t + i*256;
            int row = q >> 3, cc = (q & 7) * 8;
            u32 doff = (u32)(row*SAS + cc) * 2;
            size_t so = (size_t)row * P_ + k0 + cc;
            CPA(uAh + doff, Ah + so);
            CPA(uAl + doff, Al + so);
        }
#pragma unroll
        for (int i = 0; i < 2; i++) {                 // W tiles: 64 rows
            int q = t + i*256;
            int row = q >> 3, cc = (q & 7) * 8;
            u32 doff = (u32)(row*SAS + cc) * 2;
            size_t so = (size_t)row * P_ + k0 + cc;
            CPA(uWh + doff, WhP + so);
            CPA(uWl + doff, WlP + so);
        }
        CP_COMMIT(); CP_WAIT(0);
        __syncthreads();
#pragma unroll
        for (int ks = 0; ks < 4; ks++) {
            int k = ks * 16;
            u32 aH[2][4], aL[2][4], bH[4][2], bL[4][2];
#pragma unroll
            for (int mt = 0; mt < 2; mt++) {
                u32 off = (u32)(((arow + mt*16)*SAS + k + acolo) * 2);
                ldsm4(aH[mt][0], aH[mt][1], aH[mt][2], aH[mt][3], uAh + off);
                ldsm4(aL[mt][0], aL[mt][1], aL[mt][2], aL[mt][3], uAl + off);
            }
#pragma unroll
            for (int pr = 0; pr < 2; pr++) {
                u32 off = (u32)(((brow + pr*16)*SAS + k + bcolo) * 2);
                ldsm4(bH[2*pr][0], bH[2*pr][1], bH[2*pr+1][0], bH[2*pr+1][1], uWh + off);
                ldsm4(bL[2*pr][0], bL[2*pr][1], bL[2*pr+1][0], bL[2*pr+1][1], uWl + off);
            }
#pragma unroll
            for (int mt = 0; mt < 2; mt++)
#pragma unroll
                for (int nt = 0; nt < 4; nt++) {
                    mma_bf16(acc[mt][nt], aH[mt], bH[nt]);
                    mma_bf16(acc[mt][nt], aH[mt], bL[nt]);
                    mma_bf16(acc[mt][nt], aL[mt], bH[nt]);
                }
        }
    }

    // epilogue: *8 + b_v^T, transposed fp16 scatter to g_Df[e][n]
    int r = lane >> 2, c2_ = (lane & 3) * 2;
#pragma unroll
    for (int mt = 0; mt < 2; mt++) {
        int gm0 = m0 + wm*32 + mt*16 + r;
        int gm1 = gm0 + 8;
#pragma unroll
        for (int nt = 0; nt < 4; nt++) {
            int ge = wn*32 + nt*8 + c2_;
            size_t be0 = ((size_t)h*E_ + ge)*NL;
            size_t be1 = be0 + NL;
            size_t de0 = ((size_t)bh*E_ + ge)*NL;
            size_t de1 = de0 + NL;
            g_Df[de0 + gm0] = __float2half_rn(PRIOR*acc[mt][nt][0] + bvv[be0 + gm0]);
            g_Df[de1 + gm0] = __float2half_rn(PRIOR*acc[mt][nt][1] + bvv[be1 + gm0]);
            g_Df[de0 + gm1] = __float2half_rn(PRIOR*acc[mt][nt][2] + bvv[be0 + gm1]);
            g_Df[de1 + gm1] = __float2half_rn(PRIOR*acc[mt][nt][3] + bvv[be1 + gm1]);
        }
    }
}

// ---------------- K1: scores via mma.sync bf16 3-product, cp.async dbuf --------
__global__ __launch_bounds__(256, 1) void k_scores_mma(
    const float* __restrict__ pb, float* __restrict__ S)
{
    extern __shared__ char smraw[];
    u32 uSm = s2u(smraw);
    int t = threadIdx.x, lane = t & 31, wid = t >> 5;
    int wm = wid >> 2, wn = wid & 3;
    int n0 = blockIdx.x * 128, m0 = blockIdx.y * 128, b = blockIdx.z;

    const __nv_bfloat16* Ah = g_Uh + ((size_t)b*8192 + m0)*P_;
    const __nv_bfloat16* Al = g_Ul + ((size_t)b*8192 + m0)*P_;
    const __nv_bfloat16* Bh = g_rh + ((size_t)b*NL   + n0)*P_;
    const __nv_bfloat16* Bl = g_rl + ((size_t)b*NL   + n0)*P_;
    const u32 BUFB = 4*TILE_B;

    int arow  = wm*64 + (lane & 15);
    int acolo = (lane >> 4) * 8;
    int brow  = wn*32 + (lane & 7) + ((lane >> 4) * 8);
    int bcolo = ((lane >> 3) & 1) * 8;

    float acc[4][4][4] = {};

    auto load_chunk = [&](int c, int buf) {
        u32 sbb = uSm + (u32)buf * BUFB;
        int k0 = c * 64;
#pragma unroll
        for (int i = 0; i < 4; i++) {
            int q = t + i*256;
            int row = q >> 3, cc = (q & 7) * 8;
            u32 doff = (u32)(row*SAS + cc) * 2;
            size_t so = (size_t)row * P_ + k0 + cc;
            CPA(sbb + 0*TILE_B + doff, Ah + so);
            CPA(sbb + 1*TILE_B + doff, Al + so);
            CPA(sbb + 2*TILE_B + doff, Bh + so);
            CPA(sbb + 3*TILE_B + doff, Bl + so);
        }
    };

    load_chunk(0, 0); CP_COMMIT();
    for (int c = 0; c < 16; c++) {
        if (c < 15) { load_chunk(c+1, (c+1)&1); CP_COMMIT(); CP_WAIT(1); }
        else        { CP_WAIT(0); }
        __syncthreads();
        u32 u0 = uSm + (u32)(c&1) * BUFB;
        u32 uAh = u0, uAl = u0 + TILE_B, uBh = u0 + 2*TILE_B, uBl = u0 + 3*TILE_B;
#pragma unroll
        for (int ks = 0; ks < 4; ks++) {
            int k = ks * 16;
            u32 aH[4][4], aL[4][4], bH[4][2], bL[4][2];
#pragma unroll
            for (int mt = 0; mt < 4; mt++) {
                u32 off = (u32)(((arow + mt*16)*SAS + k + acolo) * 2);
                ldsm4(aH[mt][0], aH[mt][1], aH[mt][2], aH[mt][3], uAh + off);
                ldsm4(aL[mt][0], aL[mt][1], aL[mt][2], aL[mt][3], uAl + off);
            }
#pragma unroll
            for (int pr = 0; pr < 2; pr++) {
                u32 off = (u32)(((brow + pr*16)*SAS + k + bcolo) * 2);
                ldsm4(bH[2*pr][0], bH[2*pr][1], bH[2*pr+1][0], bH[2*pr+1][1], uBh + off);
                ldsm4(bL[2*pr][0], bL[2*pr][1], bL[2*pr+1][0], bL[2*pr+1][1], uBl + off);
            }
#pragma unroll
            for (int mt = 0; mt < 4; mt++)
#pragma unroll
                for (int nt = 0; nt < 4; nt++) {
                    mma_bf16(acc[mt][nt], aH[mt], bH[nt]);
                    mma_bf16(acc[mt][nt], aH[mt], bL[nt]);
                    mma_bf16(acc[mt][nt], aL[mt], bH[nt]);
                }
        }
        __syncthreads();
    }

    int r = lane >> 2, c2_ = (lane & 3) * 2;
#pragma unroll
    for (int mt = 0; mt < 4; mt++) {
        int gm0 = m0 + wm*64 + mt*16 + r;
        int gm1 = gm0 + 8;
        float pb0 = pb[(size_t)b*8192 + gm0];
        float pb1 = pb[(size_t)b*8192 + gm1];
        const float* ad = g_add + ((size_t)(b*H_) + (gm0 >> 9))*NL;
        float* S0 = S + ((size_t)b*8192 + gm0)*NL;
        float* S1 = S + ((size_t)b*8192 + gm1)*NL;
#pragma unroll
        for (int nt = 0; nt < 4; nt++) {
            int gn = n0 + wn*32 + nt*8 + c2_;
            float2 a2 = *(const float2*)&ad[gn];
            float2 o0, o1;
            o0.x = acc[mt][nt][0] + pb0 + a2.x;
            o0.y = acc[mt][nt][1] + pb0 + a2.y;
            o1.x = acc[mt][nt][2] + pb1 + a2.x;
            o1.y = acc[mt][nt][3] + pb1 + a2.y;
            *(float2*)&S0[gn] = o0;
            *(float2*)&S1[gn] = o1;
        }
    }
}

// ---------------- softmax (512) in place + fp16 copy ----------------
__global__ __launch_bounds__(128) void k_softmax(float* __restrict__ S)
{
    int row = blockIdx.x;
    float* p = S + (size_t)row * NL;
    int t = threadIdx.x;
    float x[4];
    float mx = -INFINITY;
#pragma unroll
    for (int i = 0; i < 4; i++) { x[i] = p[t + i*128]; mx = fmaxf(mx, x[i]); }
    __shared__ float smx[4], ssum[4];
#pragma unroll
    for (int o = 16; o > 0; o >>= 1) mx = fmaxf(mx, __shfl_xor_sync(0xffffffffu, mx, o));
    if ((t & 31) == 0) smx[t >> 5] = mx;
    __syncthreads();
    mx = fmaxf(fmaxf(smx[0], smx[1]), fmaxf(smx[2], smx[3]));
    float s = 0.f;
#pragma unroll
    for (int i = 0; i < 4; i++) { x[i] = expf(x[i] - mx); s += x[i]; }
#pragma unroll
    for (int o = 16; o > 0; o >>= 1) s += __shfl_xor_sync(0xffffffffu, s, o);
    if ((t & 31) == 0) ssum[t >> 5] = s;
    __syncthreads();
    s = ssum[0] + ssum[1] + ssum[2] + ssum[3];
    float inv = 1.0f / s;
    size_t rb = (size_t)row * NL;
#pragma unroll
    for (int i = 0; i < 4; i++) {
        float y = x[i] * inv;
        p[t + i*128] = y;
        g_Sf[rb + t + i*128] = __float2half_rn(y);
    }
}

// ---------------- K2: G = (attn @ c1) * U  (fp16 mma, cp.async dbuf) ------------
__global__ __launch_bounds__(256, 1) void k_av_mma(const float* __restrict__ U)
{
    extern __shared__ char smraw[];
    u32 uSm = s2u(smraw);
    int t = threadIdx.x, lane = t & 31, wid = t >> 5;
    int wm = wid >> 2, wn = wid & 3;
    int p0 = blockIdx.x * 128, m0 = blockIdx.y * 128, b = blockIdx.z;

    const __half* A  = g_Sf + ((size_t)b*8192 + m0)*NL;
    const __half* Bm = g_tf + ((size_t)b*P_  + p0)*NL;
    const u32 BUFB = 2*TILE_B;

    int arow  = wm*64 + (lane & 15);
    int acolo = (lane >> 4) * 8;
    int brow  = wn*32 + (lane & 7) + ((lane >> 4) * 8);
    int bcolo = ((lane >> 3) & 1) * 8;

    float acc[4][4][4] = {};

    auto load_chunk = [&](int c, int buf) {
        u32 sbb = uSm + (u32)buf * BUFB;
        int k0 = c * 64;
#pragma unroll
        for (int i = 0; i < 4; i++) {
            int q = t + i*256;
            int row = q >> 3, cc = (q & 7) * 8;
            u32 doff = (u32)(row*SAS + cc) * 2;
            size_t so = (size_t)row * NL + k0 + cc;
            CPA(sbb + 0*TILE_B + doff, A  + so);
            CPA(sbb + 1*TILE_B + doff, Bm + so);
        }
    };

    load_chunk(0, 0); CP_COMMIT();
    for (int c = 0; c < 8; c++) {
        if (c < 7) { load_chunk(c+1, (c+1)&1); CP_COMMIT(); CP_WAIT(1); }
        else       { CP_WAIT(0); }
        __syncthreads();
        u32 u0 = uSm + (u32)(c&1) * BUFB;
        u32 uA = u0, uB = u0 + TILE_B;
#pragma unroll
        for (int ks = 0; ks < 4; ks++) {
            int k = ks * 16;
            u32 aF[4][4], bF[4][2];
#pragma unroll
            for (int mt = 0; mt < 4; mt++) {
                u32 off = (u32)(((arow + mt*16)*SAS + k + acolo) * 2);
                ldsm4(aF[mt][0], aF[mt][1], aF[mt][2], aF[mt][3], uA + off);
            }
#pragma unroll
            for (int pr = 0; pr < 2; pr++) {
                u32 off = (u32)(((brow + pr*16)*SAS + k + bcolo) * 2);
                ldsm4(bF[2*pr][0], bF[2*pr][1], bF[2*pr+1][0], bF[2*pr+1][1], uB + off);
            }
#pragma unroll
            for (int mt = 0; mt < 4; mt++)
#pragma unroll
                for (int nt = 0; nt < 4; nt++)
                    mma_f16(acc[mt][nt], aF[mt], bF[nt]);
        }
        __syncthreads();
    }

    int r = lane >> 2, c2_ = (lane & 3) * 2;
#pragma unroll
    for (int mt = 0; mt < 4; mt++) {
        int gm0 = m0 + wm*64 + mt*16 + r;
        size_t ro0 = ((size_t)b*8192 + gm0)*P_;
        size_t ro1 = ro0 + 8*(size_t)P_;
#pragma unroll
        for (int nt = 0; nt < 4; nt++) {
            int gp = p0 + wn*32 + nt*8 + c2_;
            float2 u0 = *(const float2*)&U[ro0 + gp];
            float2 u1 = *(const float2*)&U[ro1 + gp];
            float gx, gy;
            __nv_bfloat16 h0, l0, h1, l1;
            gx = acc[mt][nt][0] * u0.x; gy = acc[mt][nt][1] * u0.y;
            splitbf(gx, h0, l0); splitbf(gy, h1, l1);
            *(__nv_bfloat162*)&g_Gh[ro0 + gp] = __nv_bfloat162(h0, h1);
            *(__nv_bfloat162*)&g_Gl[ro0 + gp] = __nv_bfloat162(l0, l1);
            gx = acc[mt][nt][2] * u1.x; gy = acc[mt][nt][3] * u1.y;
            splitbf(gx, h0, l0); splitbf(gy, h1, l1);
            *(__nv_bfloat162*)&g_Gh[ro1 + gp] = __nv_bfloat162(h0, h1);
            *(__nv_bfloat162*)&g_Gl[ro1 + gp] = __nv_bfloat162(l0, l1);
        }
    }
}

// ---------------- K3: out = G @ w_v^T + attn @ D  (tensorized, 128x64) ----------
__global__ __launch_bounds__(256, 1) void k_out_mma(float* __restrict__ Out)
{
    extern __shared__ char smraw[];
    u32 uSm = s2u(smraw);
    int t = threadIdx.x, lane = t & 31, wid = t >> 5;
    int wm = wid >> 1, wn = wid & 1;             // 4 x 2 warps: M=32, N=32 each
    int bh = blockIdx.y, h = bh & 15;
    int m0 = blockIdx.x * 128;

    const __nv_bfloat16* GhP = g_Gh + ((size_t)bh*NT + m0)*P_;
    const __nv_bfloat16* GlP = g_Gl + ((size_t)bh*NT + m0)*P_;
    const __nv_bfloat16* WhP = g_Wh + (size_t)h*E_*P_;
    const __nv_bfloat16* WlP = g_Wl + (size_t)h*E_*P_;
    const __half*        Sp  = g_Sf + ((size_t)bh*NT + m0)*NL;
    const __half*        Dp  = g_Df + (size_t)bh*E_*NL;

    int arow  = wm*32 + (lane & 15);
    int acolo = (lane >> 4) * 8;
    int brow  = wn*32 + (lane & 7) + ((lane >> 4) * 8);
    int bcolo = ((lane >> 3) & 1) * 8;

    float acc[2][4][4] = {};

    // ---- phase 1: G @ W^T, K = 1024, bf16 3-product ----
    u32 uGh = uSm, uGl = uGh + TILE_B, uWh = uGl + TILE_B, uWl = uWh + HTILE_B;
    for (int c = 0; c < 16; c++) {
        int k0 = c * 64;
        __syncthreads();
#pragma unroll
        for (int i = 0; i < 4; i++) {                 // G tiles: 128 rows
            int q = t + i*256;
            int row = q >> 3, cc = (q & 7) * 8;
            u32 doff = (u32)(row*SAS + cc) * 2;
            size_t so = (size_t)row * P_ + k0 + cc;
            CPA(uGh + doff, GhP + so);
            CPA(uGl + doff, GlP + so);
        }
#pragma unroll
        for (int i = 0; i < 2; i++) {                 // W tiles: 64 rows
            int q = t + i*256;
            int row = q >> 3, cc = (q & 7) * 8;
            u32 doff = (u32)(row*SAS + cc) * 2;
            size_t so = (size_t)row * P_ + k0 + cc;
            CPA(uWh + doff, WhP + so);
            CPA(uWl + doff, WlP + so);
        }
        CP_COMMIT(); CP_WAIT(0);
        __syncthreads();
#pragma unroll
        for (int ks = 0; ks < 4; ks++) {
            int k = ks * 16;
            u32 aH[2][4], aL[2][4], bH[4][2], bL[4][2];
#pragma unroll
            for (int mt = 0; mt < 2; mt++) {
                u32 off = (u32)(((arow + mt*16)*SAS + k + acolo) * 2);
                ldsm4(aH[mt][0], aH[mt][1], aH[mt][2], aH[mt][3], uGh + off);
                ldsm4(aL[mt][0], aL[mt][1], aL[mt][2], aL[mt][3], uGl + off);
            }
#pragma unroll
            for (int pr = 0; pr < 2; pr++) {
                u32 off = (u32)(((brow + pr*16)*SAS + k + bcolo) * 2);
                ldsm4(bH[2*pr][0], bH[2*pr][1], bH[2*pr+1][0], bH[2*pr+1][1], uWh + off);
                ldsm4(bL[2*pr][0], bL[2*pr][1], bL[2*pr+1][0], bL[2*pr+1][1], uWl + off);
            }
#pragma unroll
            for (int mt = 0; mt < 2; mt++)
#pragma unroll
                for (int nt = 0; nt < 4; nt++) {
                    mma_bf16(acc[mt][nt], aH[mt], bH[nt]);
                    mma_bf16(acc[mt][nt], aH[mt], bL[nt]);
                    mma_bf16(acc[mt][nt], aL[mt], bH[nt]);
                }
        }
    }

    // ---- phase 2: attn @ D^T, K = 512, fp16 ----
    u32 uA = uSm, uD = uA + TILE_B;
    for (int c = 0; c < 8; c++) {
        int k0 = c * 64;
        __syncthreads();
#pragma unroll
        for (int i = 0; i < 4; i++) {                 // attn tile: 128 rows
            int q = t + i*256;
            int row = q >> 3, cc = (q & 7) * 8;
            u32 doff = (u32)(row*SAS + cc) * 2;
            CPA(uA + doff, Sp + (size_t)row * NL + k0 + cc);
        }
#pragma unroll
        for (int i = 0; i < 2; i++) {                 // D tile: 64 rows
            int q = t + i*256;
            int row = q >> 3, cc = (q & 7) * 8;
            u32 doff = (u32)(row*SAS + cc) * 2;
            CPA(uD + doff, Dp + (size_t)row * NL + k0 + cc);
        }
        CP_COMMIT(); CP_WAIT(0);
        __syncthreads();
#pragma unroll
        for (int ks = 0; ks < 4; ks++) {
            int k = ks * 16;
            u32 aF[2][4], bF[4][2];
#pragma unroll
            for (int mt = 0; mt < 2; mt++) {
                u32 off = (u32)(((arow + mt*16)*SAS + k + acolo) * 2);
                ldsm4(aF[mt][0], aF[mt][1], aF[mt][2], aF[mt][3], uA + off);
            }
#pragma unroll
            for (int pr = 0; pr < 2; pr++) {
                u32 off = (u32)(((brow + pr*16)*SAS + k + bcolo) * 2);
                ldsm4(bF[2*pr][0], bF[2*pr][1], bF[2*pr+1][0], bF[2*pr+1][1], uD + off);
            }
#pragma unroll
            for (int mt = 0; mt < 2; mt++)
#pragma unroll
                for (int nt = 0; nt < 4; nt++)
                    mma_f16(acc[mt][nt], aF[mt], bF[nt]);
        }
    }

    int r = lane >> 2, c2_ = (lane & 3) * 2;
#pragma unroll
    for (int mt = 0; mt < 2; mt++) {
        int gm0 = m0 + wm*32 + mt*16 + r;
        float* O0 = Out + ((size_t)bh*NT + gm0)*E_;
        float* O1 = O0 + 8*(size_t)E_;
#pragma unroll
        for (int nt = 0; nt < 4; nt++) {
            int ge = wn*32 + nt*8 + c2_;
            float2 o0, o1;
            o0.x = acc[mt][nt][0]; o0.y = acc[mt][nt][1];
            o1.x = acc[mt][nt][2]; o1.y = acc[mt][nt][3];
            *(float2*)&O0[ge] = o0;
            *(float2*)&O1[ge] = o1;
        }
    }
}

// ---------------- launch ----------------
extern "C" void kernel_launch(void* const* d_in, const int* in_sizes, int n_in,
                              void* d_out, int out_size)
{
    const float* pu     = (const float*)d_in[0];  // [B,H,Nt,P]
    const float* pb     = (const float*)d_in[1];  // [B,H,Nt,1]
    const float* mu     = (const float*)d_in[2];  // [B,Nl,P]
    const float* logvar = (const float*)d_in[3];  // [B,Nl,P]
    const float* pi     = (const float*)d_in[4];  // [B,Nl,1]
    const float* wv     = (const float*)d_in[5];  // [H,E,P]
    const float* bvv    = (const float*)d_in[6];  // [H,E,Nl]
    const unsigned char* mask = (const unsigned char*)d_in[7]; // [B*H,1,Nl]

    float* out  = (float*)d_out;                  // [BH,Nt,E]
    float* attn = out + (size_t)BH*NT*E_;         // [BH,Nt,Nl]

    __nv_bfloat16 *Uh, *Ul, *Wh, *Wl;
    cudaGetSymbolAddress((void**)&Uh, g_Uh);
    cudaGetSymbolAddress((void**)&Ul, g_Ul);
    cudaGetSymbolAddress((void**)&Wh, g_Wh);
    cudaGetSymbolAddress((void**)&Wl, g_Wl);

    const int SM_SCORES = 2 * 4 * TILE_B;           // 147456 B (double buffer)
    const int SM_AV     = 2 * 2 * TILE_B;           // 73728 B
    const int SM_OUT    = 2 * TILE_B + 2 * HTILE_B; // 55296 B
    cudaFuncSetAttribute(k_scores_mma, cudaFuncAttributeMaxDynamicSharedMemorySize, SM_SCORES);
    cudaFuncSetAttribute(k_av_mma,     cudaFuncAttributeMaxDynamicSharedMemorySize, SM_AV);
    cudaFuncSetAttribute(k_out_mma,    cudaFuncAttributeMaxDynamicSharedMemorySize, SM_OUT);
    cudaFuncSetAttribute(k_D_mma,      cudaFuncAttributeMaxDynamicSharedMemorySize, SM_OUT);

    k_prep      <<<dim3(NL, B_),     256>>>(mu, logvar, pi, mask);
    k_split     <<<32768,            256>>>(pu, Uh, Ul);
    k_split     <<<1024,             256>>>(wv, Wh, Wl);
    k_D_mma     <<<dim3(NL/128, BH), 256, SM_OUT>>>(bvv);
    k_scores_mma<<<dim3(4, 64, B_),  256, SM_SCORES>>>(pb, attn);
    k_softmax   <<<BH*NT,            128>>>(attn);
    k_av_mma    <<<dim3(8, 64, B_),  256, SM_AV>>>(pu);
    k_out_mma   <<<dim3(NT/128, BH), 256, SM_OUT>>>(out);
}

// round 13
// speedup vs baseline: 3.8762x; 1.0510x over previous
#include <cuda_runtime.h>
#include <cuda_bf16.h>
#include <cuda_fp16.h>
#include <math.h>
#include <stdint.h>

#define B_  4
#define H_  16
#define NT  512
#define NL  512
#define E_  64
#define P_  1024
#define BH  (B_*H_)
#define PRIOR 8.0f

typedef unsigned int u32;

// ---------------- scratch (device globals) ----------------
__device__ __nv_bfloat16 g_Uh[(size_t)B_*8192*P_];  // U split hi  [b*8192+m][p]
__device__ __nv_bfloat16 g_Ul[(size_t)B_*8192*P_];
__device__ __nv_bfloat16 g_rh[B_*NL*P_];            // r = mu/bv hi [b][n][p]
__device__ __nv_bfloat16 g_rl[B_*NL*P_];
__device__ __half        g_tf[B_*P_*NL];            // c1^T fp16 [b][p][n]
__device__ __half        g_Sf[(size_t)BH*NT*NL];    // attn fp16 [bh*Nt+m][n]
__device__ __nv_bfloat16 g_Wh[H_*E_*P_];            // w_v split hi [h*E+e][p]
__device__ __nv_bfloat16 g_Wl[H_*E_*P_];
__device__ __nv_bfloat16 g_Gh[(size_t)BH*NT*P_];    // G split hi [bh*Nt+m][p]
__device__ __nv_bfloat16 g_Gl[(size_t)BH*NT*P_];
__device__ __half        g_Df[(size_t)BH*E_*NL];    // D^T fp16 [bh][e][n]
__device__ float g_add[BH*NL];

// ---------------- helpers ----------------
__device__ __forceinline__ u32 s2u(const void* p) {
    u32 a; asm("{ .reg .u64 t; cvta.to.shared.u64 t, %1; cvt.u32.u64 %0, t; }" : "=r"(a) : "l"(p));
    return a;
}
__device__ __forceinline__ void ldsm4(u32& r0, u32& r1, u32& r2, u32& r3, u32 a) {
    asm volatile("ldmatrix.sync.aligned.m8n8.x4.shared.b16 {%0,%1,%2,%3}, [%4];"
        : "=r"(r0), "=r"(r1), "=r"(r2), "=r"(r3) : "r"(a));
}
__device__ __forceinline__ void mma_bf16(float* c, const u32* a, const u32* b) {
    asm volatile("mma.sync.aligned.m16n8k16.row.col.f32.bf16.bf16.f32 "
        "{%0,%1,%2,%3}, {%4,%5,%6,%7}, {%8,%9}, {%0,%1,%2,%3};"
        : "+f"(c[0]), "+f"(c[1]), "+f"(c[2]), "+f"(c[3])
        : "r"(a[0]), "r"(a[1]), "r"(a[2]), "r"(a[3]), "r"(b[0]), "r"(b[1]));
}
__device__ __forceinline__ void mma_f16(float* c, const u32* a, const u32* b) {
    asm volatile("mma.sync.aligned.m16n8k16.row.col.f32.f16.f16.f32 "
        "{%0,%1,%2,%3}, {%4,%5,%6,%7}, {%8,%9}, {%0,%1,%2,%3};"
        : "+f"(c[0]), "+f"(c[1]), "+f"(c[2]), "+f"(c[3])
        : "r"(a[0]), "r"(a[1]), "r"(a[2]), "r"(a[3]), "r"(b[0]), "r"(b[1]));
}
__device__ __forceinline__ void splitbf(float x, __nv_bfloat16& h, __nv_bfloat16& l) {
    h = __float2bfloat16_rn(x);
    l = __float2bfloat16_rn(x - __bfloat162float(h));
}
#define CPA(s, g)   asm volatile("cp.async.cg.shared.global [%0], [%1], 16;" :: "r"(s), "l"(g) : "memory")
#define CP_COMMIT() asm volatile("cp.async.commit_group;" ::: "memory")
#define CP_WAIT(n)  asm volatile("cp.async.wait_group %0;" :: "n"(n) : "memory")

#define SAS     72                   // padded smem stride (elems)
#define TILE_E  (128*SAS)            // elems per 128-row tile
#define TILE_B  (TILE_E*2)           // bytes
#define HTILE_E (64*SAS)
#define HTILE_B (HTILE_E*2)

// ---------------- K0: per-(b,n) precompute + splits + reductions ----------------
__global__ __launch_bounds__(256) void k_prep(
    const float* __restrict__ mu, const float* __restrict__ logvar,
    const float* __restrict__ pi, const unsigned char* __restrict__ mask)
{
    int n = blockIdx.x, b = blockIdx.y;
    int base = (b*NL + n)*P_;
    int t = threadIdx.x;
    float s2 = 0.f, s3 = 0.f;
#pragma unroll
    for (int i = 0; i < 4; i++) {
        int p = t + i*256;
        float m  = mu[base+p];
        float v  = expf(logvar[base+p]);
        float bv = v + PRIOR;
        float inv = 1.0f / bv;
        float r  = m * inv;
        float c1 = v * inv;
        __nv_bfloat16 h, l;
        splitbf(r, h, l);
        g_rh[base+p] = h; g_rl[base+p] = l;
        g_tf[((size_t)b*P_ + p)*NL + n] = __float2half_rn(c1);
        s2 += m * m * inv;
        s3 += logf(bv);
    }
    __shared__ float red2[8], red3[8];
#pragma unroll
    for (int o = 16; o > 0; o >>= 1) {
        s2 += __shfl_down_sync(0xffffffffu, s2, o);
        s3 += __shfl_down_sync(0xffffffffu, s3, o);
    }
    if ((t & 31) == 0) { red2[t>>5] = s2; red3[t>>5] = s3; }
    __syncthreads();
    __shared__ float sbase;
    if (t == 0) {
        float a2 = 0.f, a3 = 0.f;
        for (int i = 0; i < 8; i++) { a2 += red2[i]; a3 += red3[i]; }
        float piv = pi[b*NL + n];
        float pc  = fmaxf(piv, 1.17549435e-38f);
        sbase = logf(pc) - 0.5f*a2 - 0.5f*a3;
    }
    __syncthreads();
    if (t < H_) {
        float piv = pi[b*NL + n];
        bool msk = (mask[(b*H_ + t)*NL + n] != 0) || (piv <= 0.f);
        g_add[(b*H_ + t)*NL + n] = msk ? -INFINITY : sbase;
    }
}

// ---------------- generic fp32 -> bf16 hi/lo splitter ----------------
__global__ __launch_bounds__(256) void k_split(
    const float* __restrict__ X, __nv_bfloat16* __restrict__ Xh,
    __nv_bfloat16* __restrict__ Xl)
{
    size_t i = ((size_t)blockIdx.x * 256 + threadIdx.x) * 4;
    float4 v = *(const float4*)(X + i);
    __nv_bfloat16 h[4], l[4];
    splitbf(v.x, h[0], l[0]); splitbf(v.y, h[1], l[1]);
    splitbf(v.z, h[2], l[2]); splitbf(v.w, h[3], l[3]);
    uint2 uh, ul;
    uh.x = ((u32)__bfloat16_as_ushort(h[1]) << 16) | __bfloat16_as_ushort(h[0]);
    uh.y = ((u32)__bfloat16_as_ushort(h[3]) << 16) | __bfloat16_as_ushort(h[2]);
    ul.x = ((u32)__bfloat16_as_ushort(l[1]) << 16) | __bfloat16_as_ushort(l[0]);
    ul.y = ((u32)__bfloat16_as_ushort(l[3]) << 16) | __bfloat16_as_ushort(l[2]);
    *(uint2*)&Xh[i] = uh;
    *(uint2*)&Xl[i] = ul;
}

// ---------------- K_D: D^T = 8*(r @ w_v^T) + b_v^T, bf16 mma, dbuf ----------
__global__ __launch_bounds__(256, 1) void k_D_mma(const float* __restrict__ bvv)
{
    extern __shared__ char smraw[];
    u32 uSm = s2u(smraw);
    int t = threadIdx.x, lane = t & 31, wid = t >> 5;
    int wm = wid >> 1, wn = wid & 1;             // 4 x 2 warps: 32(M) x 32(N) each
    int bh = blockIdx.y, b = bh >> 4, h = bh & 15;
    int m0 = blockIdx.x * 128;                   // n-tile

    const __nv_bfloat16* Ah = g_rh + ((size_t)b*NL + m0)*P_;
    const __nv_bfloat16* Al = g_rl + ((size_t)b*NL + m0)*P_;
    const __nv_bfloat16* WhP = g_Wh + (size_t)h*E_*P_;
    const __nv_bfloat16* WlP = g_Wl + (size_t)h*E_*P_;
    const u32 BUFB = 2*TILE_B + 2*HTILE_B;       // Ah,Al(128r) + Wh,Wl(64r)

    int arow  = wm*32 + (lane & 15);
    int acolo = (lane >> 4) * 8;
    int brow  = wn*32 + (lane & 7) + ((lane >> 4) * 8);
    int bcolo = ((lane >> 3) & 1) * 8;

    float acc[2][4][4] = {};

    auto load_chunk = [&](int c, int buf) {
        u32 sbb = uSm + (u32)buf * BUFB;
        int k0 = c * 64;
#pragma unroll
        for (int i = 0; i < 4; i++) {                 // A tiles: 128 rows
            int q = t + i*256;
            int row = q >> 3, cc = (q & 7) * 8;
            u32 doff = (u32)(row*SAS + cc) * 2;
            size_t so = (size_t)row * P_ + k0 + cc;
            CPA(sbb + 0*TILE_B + doff, Ah + so);
            CPA(sbb + 1*TILE_B + doff, Al + so);
        }
#pragma unroll
        for (int i = 0; i < 2; i++) {                 // W tiles: 64 rows
            int q = t + i*256;
            int row = q >> 3, cc = (q & 7) * 8;
            u32 doff = (u32)(row*SAS + cc) * 2;
            size_t so = (size_t)row * P_ + k0 + cc;
            CPA(sbb + 2*TILE_B + doff, WhP + so);
            CPA(sbb + 2*TILE_B + HTILE_B + doff, WlP + so);
        }
    };

    load_chunk(0, 0); CP_COMMIT();
    for (int c = 0; c < 16; c++) {
        if (c < 15) { load_chunk(c+1, (c+1)&1); CP_COMMIT(); CP_WAIT(1); }
        else        { CP_WAIT(0); }
        __syncthreads();
        u32 u0 = uSm + (u32)(c&1) * BUFB;
        u32 uAh = u0, uAl = u0 + TILE_B, uWh = u0 + 2*TILE_B, uWl = uWh + HTILE_B;
#pragma unroll
        for (int ks = 0; ks < 4; ks++) {
            int k = ks * 16;
            u32 aH[2][4], aL[2][4], bH[4][2], bL[4][2];
#pragma unroll
            for (int mt = 0; mt < 2; mt++) {
                u32 off = (u32)(((arow + mt*16)*SAS + k + acolo) * 2);
                ldsm4(aH[mt][0], aH[mt][1], aH[mt][2], aH[mt][3], uAh + off);
                ldsm4(aL[mt][0], aL[mt][1], aL[mt][2], aL[mt][3], uAl + off);
            }
#pragma unroll
            for (int pr = 0; pr < 2; pr++) {
                u32 off = (u32)(((brow + pr*16)*SAS + k + bcolo) * 2);
                ldsm4(bH[2*pr][0], bH[2*pr][1], bH[2*pr+1][0], bH[2*pr+1][1], uWh + off);
                ldsm4(bL[2*pr][0], bL[2*pr][1], bL[2*pr+1][0], bL[2*pr+1][1], uWl + off);
            }
#pragma unroll
            for (int mt = 0; mt < 2; mt++)
#pragma unroll
                for (int nt = 0; nt < 4; nt++) {
                    mma_bf16(acc[mt][nt], aH[mt], bH[nt]);
                    mma_bf16(acc[mt][nt], aH[mt], bL[nt]);
                    mma_bf16(acc[mt][nt], aL[mt], bH[nt]);
                }
        }
        __syncthreads();
    }

    // epilogue: *8 + b_v^T, transposed fp16 scatter to g_Df[e][n]
    int r = lane >> 2, c2_ = (lane & 3) * 2;
#pragma unroll
    for (int mt = 0; mt < 2; mt++) {
        int gm0 = m0 + wm*32 + mt*16 + r;
        int gm1 = gm0 + 8;
#pragma unroll
        for (int nt = 0; nt < 4; nt++) {
            int ge = wn*32 + nt*8 + c2_;
            size_t be0 = ((size_t)h*E_ + ge)*NL;
            size_t be1 = be0 + NL;
            size_t de0 = ((size_t)bh*E_ + ge)*NL;
            size_t de1 = de0 + NL;
            g_Df[de0 + gm0] = __float2half_rn(PRIOR*acc[mt][nt][0] + bvv[be0 + gm0]);
            g_Df[de1 + gm0] = __float2half_rn(PRIOR*acc[mt][nt][1] + bvv[be1 + gm0]);
            g_Df[de0 + gm1] = __float2half_rn(PRIOR*acc[mt][nt][2] + bvv[be0 + gm1]);
            g_Df[de1 + gm1] = __float2half_rn(PRIOR*acc[mt][nt][3] + bvv[be1 + gm1]);
        }
    }
}

// ---------------- K1: scores via mma.sync bf16 3-product, cp.async dbuf --------
__global__ __launch_bounds__(256, 1) void k_scores_mma(
    const float* __restrict__ pb, float* __restrict__ S)
{
    extern __shared__ char smraw[];
    u32 uSm = s2u(smraw);
    int t = threadIdx.x, lane = t & 31, wid = t >> 5;
    int wm = wid >> 2, wn = wid & 3;
    int n0 = blockIdx.x * 128, m0 = blockIdx.y * 128, b = blockIdx.z;

    const __nv_bfloat16* Ah = g_Uh + ((size_t)b*8192 + m0)*P_;
    const __nv_bfloat16* Al = g_Ul + ((size_t)b*8192 + m0)*P_;
    const __nv_bfloat16* Bh = g_rh + ((size_t)b*NL   + n0)*P_;
    const __nv_bfloat16* Bl = g_rl + ((size_t)b*NL   + n0)*P_;
    const u32 BUFB = 4*TILE_B;

    int arow  = wm*64 + (lane & 15);
    int acolo = (lane >> 4) * 8;
    int brow  = wn*32 + (lane & 7) + ((lane >> 4) * 8);
    int bcolo = ((lane >> 3) & 1) * 8;

    float acc[4][4][4] = {};

    auto load_chunk = [&](int c, int buf) {
        u32 sbb = uSm + (u32)buf * BUFB;
        int k0 = c * 64;
#pragma unroll
        for (int i = 0; i < 4; i++) {
            int q = t + i*256;
            int row = q >> 3, cc = (q & 7) * 8;
            u32 doff = (u32)(row*SAS + cc) * 2;
            size_t so = (size_t)row * P_ + k0 + cc;
            CPA(sbb + 0*TILE_B + doff, Ah + so);
            CPA(sbb + 1*TILE_B + doff, Al + so);
            CPA(sbb + 2*TILE_B + doff, Bh + so);
            CPA(sbb + 3*TILE_B + doff, Bl + so);
        }
    };

    load_chunk(0, 0); CP_COMMIT();
    for (int c = 0; c < 16; c++) {
        if (c < 15) { load_chunk(c+1, (c+1)&1); CP_COMMIT(); CP_WAIT(1); }
        else        { CP_WAIT(0); }
        __syncthreads();
        u32 u0 = uSm + (u32)(c&1) * BUFB;
        u32 uAh = u0, uAl = u0 + TILE_B, uBh = u0 + 2*TILE_B, uBl = u0 + 3*TILE_B;
#pragma unroll
        for (int ks = 0; ks < 4; ks++) {
            int k = ks * 16;
            u32 aH[4][4], aL[4][4], bH[4][2], bL[4][2];
#pragma unroll
            for (int mt = 0; mt < 4; mt++) {
                u32 off = (u32)(((arow + mt*16)*SAS + k + acolo) * 2);
                ldsm4(aH[mt][0], aH[mt][1], aH[mt][2], aH[mt][3], uAh + off);
                ldsm4(aL[mt][0], aL[mt][1], aL[mt][2], aL[mt][3], uAl + off);
            }
#pragma unroll
            for (int pr = 0; pr < 2; pr++) {
                u32 off = (u32)(((brow + pr*16)*SAS + k + bcolo) * 2);
                ldsm4(bH[2*pr][0], bH[2*pr][1], bH[2*pr+1][0], bH[2*pr+1][1], uBh + off);
                ldsm4(bL[2*pr][0], bL[2*pr][1], bL[2*pr+1][0], bL[2*pr+1][1], uBl + off);
            }
#pragma unroll
            for (int mt = 0; mt < 4; mt++)
#pragma unroll
                for (int nt = 0; nt < 4; nt++) {
                    mma_bf16(acc[mt][nt], aH[mt], bH[nt]);
                    mma_bf16(acc[mt][nt], aH[mt], bL[nt]);
                    mma_bf16(acc[mt][nt], aL[mt], bH[nt]);
                }
        }
        __syncthreads();
    }

    int r = lane >> 2, c2_ = (lane & 3) * 2;
#pragma unroll
    for (int mt = 0; mt < 4; mt++) {
        int gm0 = m0 + wm*64 + mt*16 + r;
        int gm1 = gm0 + 8;
        float pb0 = pb[(size_t)b*8192 + gm0];
        float pb1 = pb[(size_t)b*8192 + gm1];
        const float* ad = g_add + ((size_t)(b*H_) + (gm0 >> 9))*NL;
        float* S0 = S + ((size_t)b*8192 + gm0)*NL;
        float* S1 = S + ((size_t)b*8192 + gm1)*NL;
#pragma unroll
        for (int nt = 0; nt < 4; nt++) {
            int gn = n0 + wn*32 + nt*8 + c2_;
            float2 a2 = *(const float2*)&ad[gn];
            float2 o0, o1;
            o0.x = acc[mt][nt][0] + pb0 + a2.x;
            o0.y = acc[mt][nt][1] + pb0 + a2.y;
            o1.x = acc[mt][nt][2] + pb1 + a2.x;
            o1.y = acc[mt][nt][3] + pb1 + a2.y;
            *(float2*)&S0[gn] = o0;
            *(float2*)&S1[gn] = o1;
        }
    }
}

// ---------------- softmax (512) in place + fp16 copy ----------------
__global__ __launch_bounds__(128) void k_softmax(float* __restrict__ S)
{
    int row = blockIdx.x;
    float* p = S + (size_t)row * NL;
    int t = threadIdx.x;
    float x[4];
    float mx = -INFINITY;
#pragma unroll
    for (int i = 0; i < 4; i++) { x[i] = p[t + i*128]; mx = fmaxf(mx, x[i]); }
    __shared__ float smx[4], ssum[4];
#pragma unroll
    for (int o = 16; o > 0; o >>= 1) mx = fmaxf(mx, __shfl_xor_sync(0xffffffffu, mx, o));
    if ((t & 31) == 0) smx[t >> 5] = mx;
    __syncthreads();
    mx = fmaxf(fmaxf(smx[0], smx[1]), fmaxf(smx[2], smx[3]));
    float s = 0.f;
#pragma unroll
    for (int i = 0; i < 4; i++) { x[i] = expf(x[i] - mx); s += x[i]; }
#pragma unroll
    for (int o = 16; o > 0; o >>= 1) s += __shfl_xor_sync(0xffffffffu, s, o);
    if ((t & 31) == 0) ssum[t >> 5] = s;
    __syncthreads();
    s = ssum[0] + ssum[1] + ssum[2] + ssum[3];
    float inv = 1.0f / s;
    size_t rb = (size_t)row * NL;
#pragma unroll
    for (int i = 0; i < 4; i++) {
        float y = x[i] * inv;
        p[t + i*128] = y;
        g_Sf[rb + t + i*128] = __float2half_rn(y);
    }
}

// ---------------- K2: G = (attn @ c1) * U  (fp16 mma, cp.async dbuf) ------------
__global__ __launch_bounds__(256, 1) void k_av_mma(const float* __restrict__ U)
{
    extern __shared__ char smraw[];
    u32 uSm = s2u(smraw);
    int t = threadIdx.x, lane = t & 31, wid = t >> 5;
    int wm = wid >> 2, wn = wid & 3;
    int p0 = blockIdx.x * 128, m0 = blockIdx.y * 128, b = blockIdx.z;

    const __half* A  = g_Sf + ((size_t)b*8192 + m0)*NL;
    const __half* Bm = g_tf + ((size_t)b*P_  + p0)*NL;
    const u32 BUFB = 2*TILE_B;

    int arow  = wm*64 + (lane & 15);
    int acolo = (lane >> 4) * 8;
    int brow  = wn*32 + (lane & 7) + ((lane >> 4) * 8);
    int bcolo = ((lane >> 3) & 1) * 8;

    float acc[4][4][4] = {};

    auto load_chunk = [&](int c, int buf) {
        u32 sbb = uSm + (u32)buf * BUFB;
        int k0 = c * 64;
#pragma unroll
        for (int i = 0; i < 4; i++) {
            int q = t + i*256;
            int row = q >> 3, cc = (q & 7) * 8;
            u32 doff = (u32)(row*SAS + cc) * 2;
            size_t so = (size_t)row * NL + k0 + cc;
            CPA(sbb + 0*TILE_B + doff, A  + so);
            CPA(sbb + 1*TILE_B + doff, Bm + so);
        }
    };

    load_chunk(0, 0); CP_COMMIT();
    for (int c = 0; c < 8; c++) {
        if (c < 7) { load_chunk(c+1, (c+1)&1); CP_COMMIT(); CP_WAIT(1); }
        else       { CP_WAIT(0); }
        __syncthreads();
        u32 u0 = uSm + (u32)(c&1) * BUFB;
        u32 uA = u0, uB = u0 + TILE_B;
#pragma unroll
        for (int ks = 0; ks < 4; ks++) {
            int k = ks * 16;
            u32 aF[4][4], bF[4][2];
#pragma unroll
            for (int mt = 0; mt < 4; mt++) {
                u32 off = (u32)(((arow + mt*16)*SAS + k + acolo) * 2);
                ldsm4(aF[mt][0], aF[mt][1], aF[mt][2], aF[mt][3], uA + off);
            }
#pragma unroll
            for (int pr = 0; pr < 2; pr++) {
                u32 off = (u32)(((brow + pr*16)*SAS + k + bcolo) * 2);
                ldsm4(bF[2*pr][0], bF[2*pr][1], bF[2*pr+1][0], bF[2*pr+1][1], uB + off);
            }
#pragma unroll
            for (int mt = 0; mt < 4; mt++)
#pragma unroll
                for (int nt = 0; nt < 4; nt++)
                    mma_f16(acc[mt][nt], aF[mt], bF[nt]);
        }
        __syncthreads();
    }

    int r = lane >> 2, c2_ = (lane & 3) * 2;
#pragma unroll
    for (int mt = 0; mt < 4; mt++) {
        int gm0 = m0 + wm*64 + mt*16 + r;
        size_t ro0 = ((size_t)b*8192 + gm0)*P_;
        size_t ro1 = ro0 + 8*(size_t)P_;
#pragma unroll
        for (int nt = 0; nt < 4; nt++) {
            int gp = p0 + wn*32 + nt*8 + c2_;
            float2 u0 = *(const float2*)&U[ro0 + gp];
            float2 u1 = *(const float2*)&U[ro1 + gp];
            float gx, gy;
            __nv_bfloat16 h0, l0, h1, l1;
            gx = acc[mt][nt][0] * u0.x; gy = acc[mt][nt][1] * u0.y;
            splitbf(gx, h0, l0); splitbf(gy, h1, l1);
            *(__nv_bfloat162*)&g_Gh[ro0 + gp] = __nv_bfloat162(h0, h1);
            *(__nv_bfloat162*)&g_Gl[ro0 + gp] = __nv_bfloat162(l0, l1);
            gx = acc[mt][nt][2] * u1.x; gy = acc[mt][nt][3] * u1.y;
            splitbf(gx, h0, l0); splitbf(gy, h1, l1);
            *(__nv_bfloat162*)&g_Gh[ro1 + gp] = __nv_bfloat162(h0, h1);
            *(__nv_bfloat162*)&g_Gl[ro1 + gp] = __nv_bfloat162(l0, l1);
        }
    }
}

// ---------------- K3: out = G @ w_v^T + attn @ D  (tensorized, dbuf) ----------
__global__ __launch_bounds__(256, 1) void k_out_mma(float* __restrict__ Out)
{
    extern __shared__ char smraw[];
    u32 uSm = s2u(smraw);
    int t = threadIdx.x, lane = t & 31, wid = t >> 5;
    int wm = wid >> 1, wn = wid & 1;             // 4 x 2 warps: M=32, N=32 each
    int bh = blockIdx.y, h = bh & 15;
    int m0 = blockIdx.x * 128;

    const __nv_bfloat16* GhP = g_Gh + ((size_t)bh*NT + m0)*P_;
    const __nv_bfloat16* GlP = g_Gl + ((size_t)bh*NT + m0)*P_;
    const __nv_bfloat16* WhP = g_Wh + (size_t)h*E_*P_;
    const __nv_bfloat16* WlP = g_Wl + (size_t)h*E_*P_;
    const __half*        Sp  = g_Sf + ((size_t)bh*NT + m0)*NL;
    const __half*        Dp  = g_Df + (size_t)bh*E_*NL;
    const u32 BUFB = 2*TILE_B + 2*HTILE_B;

    int arow  = wm*32 + (lane & 15);
    int acolo = (lane >> 4) * 8;
    int brow  = wn*32 + (lane & 7) + ((lane >> 4) * 8);
    int bcolo = ((lane >> 3) & 1) * 8;

    float acc[2][4][4] = {};

    // ---- phase 1: G @ W^T, K = 1024, bf16 3-product, dbuf ----
    auto load1 = [&](int c, int buf) {
        u32 sbb = uSm + (u32)buf * BUFB;
        int k0 = c * 64;
#pragma unroll
        for (int i = 0; i < 4; i++) {                 // G tiles: 128 rows
            int q = t + i*256;
            int row = q >> 3, cc = (q & 7) * 8;
            u32 doff = (u32)(row*SAS + cc) * 2;
            size_t so = (size_t)row * P_ + k0 + cc;
            CPA(sbb + 0*TILE_B + doff, GhP + so);
            CPA(sbb + 1*TILE_B + doff, GlP + so);
        }
#pragma unroll
        for (int i = 0; i < 2; i++) {                 // W tiles: 64 rows
            int q = t + i*256;
            int row = q >> 3, cc = (q & 7) * 8;
            u32 doff = (u32)(row*SAS + cc) * 2;
            size_t so = (size_t)row * P_ + k0 + cc;
            CPA(sbb + 2*TILE_B + doff, WhP + so);
            CPA(sbb + 2*TILE_B + HTILE_B + doff, WlP + so);
        }
    };

    load1(0, 0); CP_COMMIT();
    for (int c = 0; c < 16; c++) {
        if (c < 15) { load1(c+1, (c+1)&1); CP_COMMIT(); CP_WAIT(1); }
        else        { CP_WAIT(0); }
        __syncthreads();
        u32 u0 = uSm + (u32)(c&1) * BUFB;
        u32 uGh = u0, uGl = u0 + TILE_B, uWh = u0 + 2*TILE_B, uWl = uWh + HTILE_B;
#pragma unroll
        for (int ks = 0; ks < 4; ks++) {
            int k = ks * 16;
            u32 aH[2][4], aL[2][4], bH[4][2], bL[4][2];
#pragma unroll
            for (int mt = 0; mt < 2; mt++) {
                u32 off = (u32)(((arow + mt*16)*SAS + k + acolo) * 2);
                ldsm4(aH[mt][0], aH[mt][1], aH[mt][2], aH[mt][3], uGh + off);
                ldsm4(aL[mt][0], aL[mt][1], aL[mt][2], aL[mt][3], uGl + off);
            }
#pragma unroll
            for (int pr = 0; pr < 2; pr++) {
                u32 off = (u32)(((brow + pr*16)*SAS + k + bcolo) * 2);
                ldsm4(bH[2*pr][0], bH[2*pr][1], bH[2*pr+1][0], bH[2*pr+1][1], uWh + off);
                ldsm4(bL[2*pr][0], bL[2*pr][1], bL[2*pr+1][0], bL[2*pr+1][1], uWl + off);
            }
#pragma unroll
            for (int mt = 0; mt < 2; mt++)
#pragma unroll
                for (int nt = 0; nt < 4; nt++) {
                    mma_bf16(acc[mt][nt], aH[mt], bH[nt]);
                    mma_bf16(acc[mt][nt], aH[mt], bL[nt]);
                    mma_bf16(acc[mt][nt], aL[mt], bH[nt]);
                }
        }
        __syncthreads();
    }

    // ---- phase 2: attn @ D^T, K = 512, fp16, dbuf ----
    auto load2 = [&](int c, int buf) {
        u32 sbb = uSm + (u32)buf * BUFB;
        int k0 = c * 64;
#pragma unroll
        for (int i = 0; i < 4; i++) {                 // attn tile: 128 rows
            int q = t + i*256;
            int row = q >> 3, cc = (q & 7) * 8;
            u32 doff = (u32)(row*SAS + cc) * 2;
            CPA(sbb + doff, Sp + (size_t)row * NL + k0 + cc);
        }
#pragma unroll
        for (int i = 0; i < 2; i++) {                 // D tile: 64 rows
            int q = t + i*256;
            int row = q >> 3, cc = (q & 7) * 8;
            u32 doff = (u32)(row*SAS + cc) * 2;
            CPA(sbb + TILE_B + doff, Dp + (size_t)row * NL + k0 + cc);
        }
    };

    load2(0, 0); CP_COMMIT();
    for (int c = 0; c < 8; c++) {
        if (c < 7) { load2(c+1, (c+1)&1); CP_COMMIT(); CP_WAIT(1); }
        else       { CP_WAIT(0); }
        __syncthreads();
        u32 u0 = uSm + (u32)(c&1) * BUFB;
        u32 uA = u0, uD = u0 + TILE_B;
#pragma unroll
        for (int ks = 0; ks < 4; ks++) {
            int k = ks * 16;
            u32 aF[2][4], bF[4][2];
#pragma unroll
            for (int mt = 0; mt < 2; mt++) {
                u32 off = (u32)(((arow + mt*16)*SAS + k + acolo) * 2);
                ldsm4(aF[mt][0], aF[mt][1], aF[mt][2], aF[mt][3], uA + off);
            }
#pragma unroll
            for (int pr = 0; pr < 2; pr++) {
                u32 off = (u32)(((brow + pr*16)*SAS + k + bcolo) * 2);
                ldsm4(bF[2*pr][0], bF[2*pr][1], bF[2*pr+1][0], bF[2*pr+1][1], uD + off);
            }
#pragma unroll
            for (int mt = 0; mt < 2; mt++)
#pragma unroll
                for (int nt = 0; nt < 4; nt++)
                    mma_f16(acc[mt][nt], aF[mt], bF[nt]);
        }
        __syncthreads();
    }

    int r = lane >> 2, c2_ = (lane & 3) * 2;
#pragma unroll
    for (int mt = 0; mt < 2; mt++) {
        int gm0 = m0 + wm*32 + mt*16 + r;
        float* O0 = Out + ((size_t)bh*NT + gm0)*E_;
        float* O1 = O0 + 8*(size_t)E_;
#pragma unroll
        for (int nt = 0; nt < 4; nt++) {
            int ge = wn*32 + nt*8 + c2_;
            float2 o0, o1;
            o0.x = acc[mt][nt][0]; o0.y = acc[mt][nt][1];
            o1.x = acc[mt][nt][2]; o1.y = acc[mt][nt][3];
            *(float2*)&O0[ge] = o0;
            *(float2*)&O1[ge] = o1;
        }
    }
}

// ---------------- launch ----------------
extern "C" void kernel_launch(void* const* d_in, const int* in_sizes, int n_in,
                              void* d_out, int out_size)
{
    const float* pu     = (const float*)d_in[0];  // [B,H,Nt,P]
    const float* pb     = (const float*)d_in[1];  // [B,H,Nt,1]
    const float* mu     = (const float*)d_in[2];  // [B,Nl,P]
    const float* logvar = (const float*)d_in[3];  // [B,Nl,P]
    const float* pi     = (const float*)d_in[4];  // [B,Nl,1]
    const float* wv     = (const float*)d_in[5];  // [H,E,P]
    const float* bvv    = (const float*)d_in[6];  // [H,E,Nl]
    const unsigned char* mask = (const unsigned char*)d_in[7]; // [B*H,1,Nl]

    float* out  = (float*)d_out;                  // [BH,Nt,E]
    float* attn = out + (size_t)BH*NT*E_;         // [BH,Nt,Nl]

    __nv_bfloat16 *Uh, *Ul, *Wh, *Wl;
    cudaGetSymbolAddress((void**)&Uh, g_Uh);
    cudaGetSymbolAddress((void**)&Ul, g_Ul);
    cudaGetSymbolAddress((void**)&Wh, g_Wh);
    cudaGetSymbolAddress((void**)&Wl, g_Wl);

    const int SM_SCORES = 2 * 4 * TILE_B;                  // 147456 B
    const int SM_AV     = 2 * 2 * TILE_B;                  // 73728 B
    const int SM_OUT    = 2 * (2 * TILE_B + 2 * HTILE_B);  // 110592 B (dbuf)
    cudaFuncSetAttribute(k_scores_mma, cudaFuncAttributeMaxDynamicSharedMemorySize, SM_SCORES);
    cudaFuncSetAttribute(k_av_mma,     cudaFuncAttributeMaxDynamicSharedMemorySize, SM_AV);
    cudaFuncSetAttribute(k_out_mma,    cudaFuncAttributeMaxDynamicSharedMemorySize, SM_OUT);
    cudaFuncSetAttribute(k_D_mma,      cudaFuncAttributeMaxDynamicSharedMemorySize, SM_OUT);

    k_prep      <<<dim3(NL, B_),     256>>>(mu, logvar, pi, mask);
    k_split     <<<32768,            256>>>(pu, Uh, Ul);
    k_split     <<<1024,             256>>>(wv, Wh, Wl);
    k_D_mma     <<<dim3(NL/128, BH), 256, SM_OUT>>>(bvv);
    k_scores_mma<<<dim3(4, 64, B_),  256, SM_SCORES>>>(pb, attn);
    k_softmax   <<<BH*NT,            128>>>(attn);
    k_av_mma    <<<dim3(8, 64, B_),  256, SM_AV>>>(pu);
    k_out_mma   <<<dim3(NT/128, BH), 256, SM_OUT>>>(out);
}